// round 12
// baseline (speedup 1.0000x reference)
#include <cuda_runtime.h>
#include <cuda_fp16.h>
#include <cstdint>

// ---------------- problem constants ----------------
#define BB     8
#define NQ_    256
#define DIM_   768
#define KVD_   1024
#define HH     8
#define DH_    64
#define INNER_ 512
#define TM_    8192
#define BNQ    2048
#define BTM    65536
#define LN_EPS 1e-5f

// q scale folded with log2(e): 0.125 * 1.4426950408889634
#define QSCALE 0.18033688011112043f

#define NSPLIT 4
#define KVSPLIT (TM_ / NSPLIT)              // 2048

// ---------------- scratch (device globals) ----------------
__device__ __half g_xn[BNQ * DIM_];
__device__ __half g_kvn[(size_t)BTM * KVD_];
__device__ __half g_wqT[INNER_ * DIM_];
__device__ __half g_wkvT[1024 * KVD_];
__device__ __half g_woT[DIM_ * INNER_];
__device__ __half g_qbuf[BNQ * INNER_];
__device__ __half g_kvp[(size_t)BTM * 1024];
__device__ __half g_att[BNQ * INNER_];
__device__ float  g_attp[NSPLIT * BNQ * INNER_];   // partial unnormalized O (16MB)
__device__ float  g_lsum[NSPLIT * BNQ * HH];       // partial row sums

// ---------------- helpers ----------------
__device__ __forceinline__ uint32_t packh2(float lo, float hi) {
    uint32_t r;
    asm("cvt.rn.f16x2.f32 %0, %1, %2;" : "=r"(r) : "f"(hi), "f"(lo));
    return r;
}

__device__ __forceinline__ uint32_t h2e2(uint32_t x) {
    __half2 h = *reinterpret_cast<__half2*>(&x);
    h = h2exp2(h);
    return *reinterpret_cast<uint32_t*>(&h);
}

__device__ __forceinline__ float2 h22f2(uint32_t x) {
    __half2 h = *reinterpret_cast<__half2*>(&x);
    return __half22float2(h);
}

__device__ __forceinline__ void mma16(float c[4], const uint32_t a[4],
                                      uint32_t b0, uint32_t b1) {
    asm volatile("mma.sync.aligned.m16n8k16.row.col.f32.f16.f16.f32 "
        "{%0,%1,%2,%3}, {%4,%5,%6,%7}, {%8,%9}, {%0,%1,%2,%3};"
        : "+f"(c[0]), "+f"(c[1]), "+f"(c[2]), "+f"(c[3])
        : "r"(a[0]), "r"(a[1]), "r"(a[2]), "r"(a[3]), "r"(b0), "r"(b1));
}

__device__ __forceinline__ void cpa(uint32_t dst, const void* src) {
    asm volatile("cp.async.cg.shared.global [%0], [%1], 16;" :: "r"(dst), "l"(src));
}
#define CP_COMMIT asm volatile("cp.async.commit_group;")
#define CP_WAIT1  asm volatile("cp.async.wait_group 1;")
#define CP_WAIT2  asm volatile("cp.async.wait_group 2;")

__device__ __forceinline__ uint32_t smem_u32(const void* p) {
    return (uint32_t)__cvta_generic_to_shared(p);
}

#define LDSM_X4(r0, r1, r2, r3, addr) \
    asm volatile("ldmatrix.sync.aligned.m8n8.x4.shared.b16 {%0,%1,%2,%3}, [%4];" \
                 : "=r"(r0), "=r"(r1), "=r"(r2), "=r"(r3) : "r"(addr))
#define LDSM_T(r0, r1, r2, r3, addr) \
    asm volatile("ldmatrix.sync.aligned.m8n8.x4.trans.shared.b16 {%0,%1,%2,%3}, [%4];" \
                 : "=r"(r0), "=r"(r1), "=r"(r2), "=r"(r3) : "r"(addr))

// ---------------- fused LayerNorm + fp16 convert ----------------
template <int RL>
__global__ __launch_bounds__(256) void ln_conv(const float* __restrict__ X,
                                               const float* __restrict__ gam,
                                               const float* __restrict__ bet,
                                               __half* __restrict__ Y) {
    const int row = blockIdx.x;
    const int i = threadIdx.x;
    const bool act = i < RL / 4;
    float4 v = make_float4(0.f, 0.f, 0.f, 0.f);
    if (act) v = reinterpret_cast<const float4*>(X + (size_t)row * RL)[i];
    float s  = (v.x + v.y) + (v.z + v.w);
    float ss = v.x * v.x + v.y * v.y + v.z * v.z + v.w * v.w;
    #pragma unroll
    for (int o = 16; o; o >>= 1) {
        s  += __shfl_xor_sync(0xffffffffu, s, o);
        ss += __shfl_xor_sync(0xffffffffu, ss, o);
    }
    __shared__ float sh[16];
    __shared__ float st[2];
    const int w = i >> 5, l = i & 31;
    if (l == 0) { sh[w] = s; sh[w + 8] = ss; }
    __syncthreads();
    if (i == 0) {
        float S = 0.f, SS = 0.f;
        #pragma unroll
        for (int k = 0; k < 8; k++) { S += sh[k]; SS += sh[k + 8]; }
        const float m = S / (float)RL;
        st[0] = m;
        st[1] = rsqrtf(SS / (float)RL - m * m + LN_EPS);
    }
    __syncthreads();
    if (act) {
        const float m = st[0], r = st[1];
        const float4 gv = reinterpret_cast<const float4*>(gam)[i];
        const float4 bv = reinterpret_cast<const float4*>(bet)[i];
        uint2 o;
        o.x = packh2((v.x - m) * r * gv.x + bv.x, (v.y - m) * r * gv.y + bv.y);
        o.y = packh2((v.z - m) * r * gv.z + bv.z, (v.w - m) * r * gv.w + bv.w);
        *reinterpret_cast<uint2*>(Y + (size_t)row * RL + i * 4) = o;
    }
}

// ---------------- weight transpose ----------------
__global__ __launch_bounds__(256) void wconvT(const float* __restrict__ W,
                                              __half* __restrict__ Wt,
                                              int K, int N) {
    __shared__ __half t[32][33];
    const int tx = threadIdx.x, ty = threadIdx.y;
    const int k0 = blockIdx.y * 32, n0 = blockIdx.x * 32;
    #pragma unroll
    for (int i = 0; i < 4; i++)
        t[ty + i * 8][tx] = __float2half_rn(W[(size_t)(k0 + ty + i * 8) * N + n0 + tx]);
    __syncthreads();
    #pragma unroll
    for (int i = 0; i < 4; i++)
        Wt[(size_t)(n0 + ty + i * 8) * K + k0 + tx] = t[tx][ty + i * 8];
}

// ====== BIG GEMM: 256x128 CTA, 512 threads (16 warps as 8x2, 32x64 each), ======
// ====== BK=32, 4-stage, prefetch after compute, single sync per k-tile =========
#define SAH 40
#define BG_A_H (256 * SAH)                  // 10240 halves
#define BG_B_H (128 * SAH)                  // 5120 halves
#define BG_STG_H (BG_A_H + BG_B_H)          // 15360 halves / stage
#define BG_SMEM (4 * BG_STG_H * 2)          // 122880 B

__global__ __launch_bounds__(512, 1) void gemm_f16_big(
    const __half* __restrict__ A, const __half* __restrict__ Bt,
    __half* __restrict__ C, int N, int K) {
    extern __shared__ __half smh[];
    const uint32_t s_b = smem_u32(smh);

    const int tid = threadIdx.x;
    const int warp = tid >> 5, lane = tid & 31;
    const int g = lane >> 2, q = lane & 3;
    const int wm = (warp >> 1) * 32;
    const int wn = (warp & 1) * 64;
    const int bm0 = blockIdx.y * 256;
    const int bn0 = blockIdx.x * 128;
    const __half* Ab = A + (size_t)bm0 * K;
    const __half* Bb = Bt + (size_t)bn0 * K;

    const int lmA = (lane & 15) * SAH + ((lane >> 4) << 3);
    const int lmB = (((lane >> 4) << 3) + (lane & 7)) * SAH + (((lane >> 3) & 1) << 3);

    auto issue = [&](int stage, int kt) {
        const uint32_t base = s_b + stage * BG_STG_H * 2;
        #pragma unroll
        for (int c = 0; c < 2; c++) {
            const int cid = tid + c * 512;
            const int row = cid >> 2, c8 = (cid & 3) * 8;
            cpa(base + (uint32_t)(row * SAH + c8) * 2,
                Ab + (size_t)row * K + kt + c8);
        }
        {
            const int row = tid >> 2, c8 = (tid & 3) * 8;
            cpa(base + BG_A_H * 2 + (uint32_t)(row * SAH + c8) * 2,
                Bb + (size_t)row * K + kt + c8);
        }
    };

    float acc[2][8][4];
    #pragma unroll
    for (int mt = 0; mt < 2; mt++)
        #pragma unroll
        for (int nt = 0; nt < 8; nt++)
            #pragma unroll
            for (int i = 0; i < 4; i++) acc[mt][nt][i] = 0.f;

    const int nk = K / 32;
    issue(0, 0);  CP_COMMIT;
    issue(1, 32); CP_COMMIT;
    issue(2, 64); CP_COMMIT;

    for (int t = 0; t < nk; t++) {
        CP_WAIT2;
        __syncthreads();
        const uint32_t cAb = s_b + ((t & 3) * BG_STG_H) * 2;
        const uint32_t cBb = cAb + BG_A_H * 2;
        #pragma unroll
        for (int kk = 0; kk < 32; kk += 16) {
            uint32_t af[2][4];
            #pragma unroll
            for (int mt = 0; mt < 2; mt++)
                LDSM_X4(af[mt][0], af[mt][1], af[mt][2], af[mt][3],
                        cAb + (uint32_t)((wm + mt * 16) * SAH + kk + lmA) * 2);
            #pragma unroll
            for (int p = 0; p < 4; p++) {
                uint32_t b0, b1, b2, b3;
                LDSM_X4(b0, b1, b2, b3,
                        cBb + (uint32_t)((wn + p * 16) * SAH + kk + lmB) * 2);
                mma16(acc[0][2 * p],     af[0], b0, b1);
                mma16(acc[1][2 * p],     af[1], b0, b1);
                mma16(acc[0][2 * p + 1], af[0], b2, b3);
                mma16(acc[1][2 * p + 1], af[1], b2, b3);
            }
        }
        if (t + 3 < nk) issue((t + 3) & 3, (t + 3) * 32);
        CP_COMMIT;
    }

    #pragma unroll
    for (int mt = 0; mt < 2; mt++)
        #pragma unroll
        for (int nt = 0; nt < 8; nt++) {
            const int r0 = bm0 + wm + mt * 16 + g;
            const int c0 = bn0 + wn + nt * 8 + 2 * q;
            *reinterpret_cast<uint32_t*>(C + (size_t)r0 * N + c0) =
                packh2(acc[mt][nt][0], acc[mt][nt][1]);
            *reinterpret_cast<uint32_t*>(C + (size_t)(r0 + 8) * N + c0) =
                packh2(acc[mt][nt][2], acc[mt][nt][3]);
        }
}

// ---------------- small pipelined fp16 GEMM (128x128x32, 3-stage) ----------------
#define ASTG_H (128 * SAH)
#define STAGE_H (2 * ASTG_H)
#define GEMM_SMEM (3 * STAGE_H * 2)   // 61440 B

template <bool OTF>
__global__ __launch_bounds__(256, 2) void gemm_f16(
    const __half* __restrict__ A, const __half* __restrict__ Bt,
    void* __restrict__ Cv, int N, int K, float alpha) {
    extern __shared__ __half smh[];
    const uint32_t s_b = smem_u32(smh);

    const int tid = threadIdx.x;
    const int warp = tid >> 5, lane = tid & 31;
    const int g = lane >> 2, q = lane & 3;
    const int wm = (warp >> 1) * 32;
    const int wn = (warp & 1) * 64;
    const int bm0 = blockIdx.y * 128;
    const int bn0 = blockIdx.x * 128;
    const __half* Ab = A + (size_t)bm0 * K;
    const __half* Bb = Bt + (size_t)bn0 * K;

    const int lmA = (lane & 15) * SAH + ((lane >> 4) << 3);
    const int lmB = (((lane >> 4) << 3) + (lane & 7)) * SAH + (((lane >> 3) & 1) << 3);

    auto issue = [&](int stage, int kt) {
        const uint32_t base = s_b + stage * STAGE_H * 2;
        #pragma unroll
        for (int c = 0; c < 2; c++) {
            const int cid = tid + c * 256;
            const int row = cid >> 2, c8 = (cid & 3) * 8;
            cpa(base + (uint32_t)(row * SAH + c8) * 2,
                Ab + (size_t)row * K + kt + c8);
            cpa(base + ASTG_H * 2 + (uint32_t)(row * SAH + c8) * 2,
                Bb + (size_t)row * K + kt + c8);
        }
    };

    float acc[2][8][4];
    #pragma unroll
    for (int mt = 0; mt < 2; mt++)
        #pragma unroll
        for (int nt = 0; nt < 8; nt++)
            #pragma unroll
            for (int i = 0; i < 4; i++) acc[mt][nt][i] = 0.f;

    const int nk = K / 32;
    issue(0, 0);  CP_COMMIT;
    issue(1, 32); CP_COMMIT;

    for (int t = 0; t < nk; t++) {
        if (t + 2 < nk) issue((t + 2) % 3, (t + 2) * 32);
        CP_COMMIT;
        CP_WAIT2;
        __syncthreads();
        const uint32_t cAb = s_b + ((t % 3) * STAGE_H) * 2;
        const uint32_t cBb = cAb + ASTG_H * 2;
        #pragma unroll
        for (int kk = 0; kk < 32; kk += 16) {
            uint32_t af[2][4];
            #pragma unroll
            for (int mt = 0; mt < 2; mt++)
                LDSM_X4(af[mt][0], af[mt][1], af[mt][2], af[mt][3],
                        cAb + (uint32_t)((wm + mt * 16) * SAH + kk + lmA) * 2);
            #pragma unroll
            for (int p = 0; p < 4; p++) {
                uint32_t b0, b1, b2, b3;
                LDSM_X4(b0, b1, b2, b3,
                        cBb + (uint32_t)((wn + p * 16) * SAH + kk + lmB) * 2);
                mma16(acc[0][2 * p],     af[0], b0, b1);
                mma16(acc[1][2 * p],     af[1], b0, b1);
                mma16(acc[0][2 * p + 1], af[0], b2, b3);
                mma16(acc[1][2 * p + 1], af[1], b2, b3);
            }
        }
        __syncthreads();
    }

    #pragma unroll
    for (int mt = 0; mt < 2; mt++)
        #pragma unroll
        for (int nt = 0; nt < 8; nt++) {
            const int r0 = bm0 + wm + mt * 16 + g;
            const int c0 = bn0 + wn + nt * 8 + 2 * q;
            if (OTF) {
                __half* C = (__half*)Cv;
                *reinterpret_cast<uint32_t*>(C + (size_t)r0 * N + c0) =
                    packh2(acc[mt][nt][0] * alpha, acc[mt][nt][1] * alpha);
                *reinterpret_cast<uint32_t*>(C + (size_t)(r0 + 8) * N + c0) =
                    packh2(acc[mt][nt][2] * alpha, acc[mt][nt][3] * alpha);
            } else {
                float* C = (float*)Cv;
                *reinterpret_cast<float2*>(C + (size_t)r0 * N + c0) =
                    make_float2(acc[mt][nt][0] * alpha, acc[mt][nt][1] * alpha);
                *reinterpret_cast<float2*>(C + (size_t)(r0 + 8) * N + c0) =
                    make_float2(acc[mt][nt][2] * alpha, acc[mt][nt][3] * alpha);
            }
        }
}

// ---------------- flash attention v3: Q-tile 256, KV-split 4, partial outputs ----
#define JC   64
#define KST  88
#define TILE_H (JC * KST)
#define KOFF(buf) ((buf) * TILE_H)
#define VOFF(buf) (2 * TILE_H + (buf) * TILE_H)
#define ATT_SMEM (4 * TILE_H * 2)

__global__ __launch_bounds__(256, 1) void attention_kernel(
    const __half* __restrict__ Q, const __half* __restrict__ KV,
    float* __restrict__ Op, float* __restrict__ Lp) {
    extern __shared__ __half smh[];
    const uint32_t s_b = smem_u32(smh);

    const int bh = blockIdx.x;
    const int b = bh >> 3, h = bh & 7;
    const int split = blockIdx.y;
    const int tid = threadIdx.x, warp = tid >> 5, lane = tid & 31;
    const int g = lane >> 2, q = lane & 3;

    const __half* Kg = KV + ((size_t)(b * TM_) + split * KVSPLIT) * 1024 + h * DH_;
    const __half* Vg = Kg + INNER_;

    auto issue = [&](int buf, int j0) {
        #pragma unroll
        for (int p = 0; p < 2; p++) {
            const int cid = tid + p * 256;
            const int jj = cid >> 3, c8 = (cid & 7) * 8;
            cpa(s_b + (uint32_t)(KOFF(buf) + jj * KST + c8) * 2,
                Kg + (size_t)(j0 + jj) * 1024 + c8);
            cpa(s_b + (uint32_t)(VOFF(buf) + jj * KST + c8) * 2,
                Vg + (size_t)(j0 + jj) * 1024 + c8);
        }
    };

    const int qrow0 = b * NQ_ + warp * 32;
    uint32_t qa[2][4][4];
    #pragma unroll
    for (int mt = 0; mt < 2; mt++) {
        const __half* Qb = Q + (size_t)(qrow0 + mt * 16) * INNER_ + h * DH_;
        #pragma unroll
        for (int ks = 0; ks < 4; ks++) {
            const __half* p = Qb + (size_t)g * INNER_ + ks * 16 + 2 * q;
            qa[mt][ks][0] = *reinterpret_cast<const uint32_t*>(p);
            qa[mt][ks][1] = *reinterpret_cast<const uint32_t*>(p + 8 * INNER_);
            qa[mt][ks][2] = *reinterpret_cast<const uint32_t*>(p + 8);
            qa[mt][ks][3] = *reinterpret_cast<const uint32_t*>(p + 8 * INNER_ + 8);
        }
    }

    float oacc[2][8][4];
    #pragma unroll
    for (int mt = 0; mt < 2; mt++)
        #pragma unroll
        for (int nt = 0; nt < 8; nt++)
            #pragma unroll
            for (int i = 0; i < 4; i++) oacc[mt][nt][i] = 0.f;
    float lr[2][2] = {{0.f, 0.f}, {0.f, 0.f}};

    const int lmB = (((lane >> 4) << 3) + (lane & 7)) * KST + (((lane >> 3) & 1) << 3);
    const int lm_row = lane & 15;
    const int lm_col = (lane >> 4) * 8;

    const int NC = KVSPLIT / JC;   // 32
    issue(0, 0); CP_COMMIT;

    for (int jc = 0; jc < NC; jc++) {
        const int buf = jc & 1;
        if (jc + 1 < NC) issue(buf ^ 1, (jc + 1) * JC);
        CP_COMMIT;
        CP_WAIT1;
        __syncthreads();

        float sacc[2][8][4];
        #pragma unroll
        for (int mt = 0; mt < 2; mt++)
            #pragma unroll
            for (int nt = 0; nt < 8; nt++)
                #pragma unroll
                for (int i = 0; i < 4; i++) sacc[mt][nt][i] = 0.f;
        const uint32_t kb = s_b + (uint32_t)KOFF(buf) * 2;
        #pragma unroll
        for (int ks = 0; ks < 4; ks++) {
            #pragma unroll
            for (int p = 0; p < 4; p++) {
                uint32_t b0, b1, b2, b3;
                LDSM_X4(b0, b1, b2, b3,
                        kb + (uint32_t)(p * 16 * KST + ks * 16 + lmB) * 2);
                #pragma unroll
                for (int mt = 0; mt < 2; mt++) {
                    mma16(sacc[mt][2 * p],     qa[mt][ks], b0, b1);
                    mma16(sacc[mt][2 * p + 1], qa[mt][ks], b2, b3);
                }
            }
        }

        uint32_t pa[2][4][4];
        #pragma unroll
        for (int mt = 0; mt < 2; mt++) {
            float ls0 = 0.f, ls1 = 0.f;
            #pragma unroll
            for (int ks = 0; ks < 4; ks++) {
                pa[mt][ks][0] = h2e2(packh2(sacc[mt][2 * ks][0],     sacc[mt][2 * ks][1]));
                pa[mt][ks][1] = h2e2(packh2(sacc[mt][2 * ks][2],     sacc[mt][2 * ks][3]));
                pa[mt][ks][2] = h2e2(packh2(sacc[mt][2 * ks + 1][0], sacc[mt][2 * ks + 1][1]));
                pa[mt][ks][3] = h2e2(packh2(sacc[mt][2 * ks + 1][2], sacc[mt][2 * ks + 1][3]));
                float2 a0 = h22f2(pa[mt][ks][0]), a2 = h22f2(pa[mt][ks][2]);
                ls0 += (a0.x + a0.y) + (a2.x + a2.y);
                float2 a1 = h22f2(pa[mt][ks][1]), a3 = h22f2(pa[mt][ks][3]);
                ls1 += (a1.x + a1.y) + (a3.x + a3.y);
            }
            lr[mt][0] += ls0;
            lr[mt][1] += ls1;
        }

        const uint32_t vbase =
            s_b + (uint32_t)(VOFF(buf) + lm_row * KST + lm_col) * 2;
        #pragma unroll
        for (int ks = 0; ks < 4; ks++) {
            #pragma unroll
            for (int dg = 0; dg < 4; dg++) {
                uint32_t v0, v1, v2, v3;
                LDSM_T(v0, v1, v2, v3,
                       vbase + (uint32_t)(ks * 16 * KST + dg * 16) * 2);
                #pragma unroll
                for (int mt = 0; mt < 2; mt++) {
                    mma16(oacc[mt][dg * 2],     pa[mt][ks], v0, v1);
                    mma16(oacc[mt][dg * 2 + 1], pa[mt][ks], v2, v3);
                }
            }
        }
        __syncthreads();
    }

    float* Ob = Op + (size_t)split * BNQ * INNER_;
    #pragma unroll
    for (int mt = 0; mt < 2; mt++) {
        const int r0 = qrow0 + mt * 16 + g;
        #pragma unroll
        for (int nt = 0; nt < 8; nt++) {
            const int c0 = h * DH_ + nt * 8 + 2 * q;
            *reinterpret_cast<float2*>(Ob + (size_t)r0 * INNER_ + c0) =
                make_float2(oacc[mt][nt][0], oacc[mt][nt][1]);
            *reinterpret_cast<float2*>(Ob + (size_t)(r0 + 8) * INNER_ + c0) =
                make_float2(oacc[mt][nt][2], oacc[mt][nt][3]);
        }
        float l0 = lr[mt][0], l1 = lr[mt][1];
        #pragma unroll
        for (int o = 1; o < 4; o <<= 1) {
            l0 += __shfl_xor_sync(0xffffffffu, l0, o);
            l1 += __shfl_xor_sync(0xffffffffu, l1, o);
        }
        if (q == 0) {
            Lp[((size_t)split * BNQ + r0) * HH + h]     = l0;
            Lp[((size_t)split * BNQ + r0 + 8) * HH + h] = l1;
        }
    }
}

// ---------------- attention reduce: att = sum(Oi)/sum(li), fp16 ----------------
__global__ __launch_bounds__(256) void att_reduce(
    const float* __restrict__ Op, const float* __restrict__ Lp,
    __half* __restrict__ att) {
    const int r = blockIdx.x;
    const int c = threadIdx.x * 2;
    const int h = c >> 6;
    float ax = 0.f, ay = 0.f, l = 0.f;
    #pragma unroll
    for (int s = 0; s < NSPLIT; s++) {
        const float2 a = *reinterpret_cast<const float2*>(
            Op + ((size_t)s * BNQ + r) * INNER_ + c);
        ax += a.x; ay += a.y;
        l += Lp[((size_t)s * BNQ + r) * HH + h];
    }
    const float inv = 1.f / l;
    *reinterpret_cast<uint32_t*>(att + (size_t)r * INNER_ + c) =
        packh2(ax * inv, ay * inv);
}

// ---------------- launch ----------------
extern "C" void kernel_launch(void* const* d_in, const int* in_sizes, int n_in,
                              void* d_out, int out_size) {
    const float* x    = (const float*)d_in[0];
    const float* k_v  = (const float*)d_in[1];
    const float* g_q  = (const float*)d_in[2];
    const float* b_q  = (const float*)d_in[3];
    const float* g_kv = (const float*)d_in[4];
    const float* b_kv = (const float*)d_in[5];
    const float* Wq   = (const float*)d_in[6];
    const float* Wkv  = (const float*)d_in[7];
    const float* Wo   = (const float*)d_in[8];
    float* out = (float*)d_out;

    __half *xn, *kvn, *wqT, *wkvT, *woT, *qbuf, *kvp, *att;
    float *attp, *lsum;
    cudaGetSymbolAddress((void**)&xn,   g_xn);
    cudaGetSymbolAddress((void**)&kvn,  g_kvn);
    cudaGetSymbolAddress((void**)&wqT,  g_wqT);
    cudaGetSymbolAddress((void**)&wkvT, g_wkvT);
    cudaGetSymbolAddress((void**)&woT,  g_woT);
    cudaGetSymbolAddress((void**)&qbuf, g_qbuf);
    cudaGetSymbolAddress((void**)&kvp,  g_kvp);
    cudaGetSymbolAddress((void**)&att,  g_att);
    cudaGetSymbolAddress((void**)&attp, g_attp);
    cudaGetSymbolAddress((void**)&lsum, g_lsum);

    cudaFuncSetAttribute(gemm_f16<true>,
                         cudaFuncAttributeMaxDynamicSharedMemorySize, GEMM_SMEM);
    cudaFuncSetAttribute(gemm_f16<false>,
                         cudaFuncAttributeMaxDynamicSharedMemorySize, GEMM_SMEM);
    cudaFuncSetAttribute(gemm_f16_big,
                         cudaFuncAttributeMaxDynamicSharedMemorySize, BG_SMEM);
    cudaFuncSetAttribute(attention_kernel,
                         cudaFuncAttributeMaxDynamicSharedMemorySize, ATT_SMEM);

    // 0,1: LayerNorm + fp16 convert
    ln_conv<KVD_><<<BTM, 256>>>(k_v, g_kv, b_kv, kvn);
    ln_conv<DIM_><<<BNQ, 256>>>(x, g_q, b_q, xn);

    // 2: Wkv^T
    wconvT<<<dim3(1024 / 32, KVD_ / 32), dim3(32, 8)>>>(Wkv, wkvT, KVD_, 1024);

    // 3 (profiled slot): kv projection, 512-thread big GEMM
    gemm_f16_big<<<dim3(1024 / 128, BTM / 256), 512, BG_SMEM>>>(
        kvn, wkvT, kvp, 1024, KVD_);

    // 4,5: remaining weight transposes
    wconvT<<<dim3(INNER_ / 32, DIM_ / 32), dim3(32, 8)>>>(Wq, wqT, DIM_, INNER_);
    wconvT<<<dim3(DIM_ / 32, INNER_ / 32), dim3(32, 8)>>>(Wo, woT, INNER_, DIM_);

    // 6: q proj with exp2-folded scale
    gemm_f16<true><<<dim3(INNER_ / 128, BNQ / 128), 256, GEMM_SMEM>>>(
        xn, wqT, qbuf, INNER_, DIM_, QSCALE);

    // 7: flash attention v3 (4-way KV split, partial outputs)
    attention_kernel<<<dim3(BB * HH, NSPLIT), 256, ATT_SMEM>>>(qbuf, kvp, attp, lsum);

    // 8: combine partials
    att_reduce<<<BNQ, 256>>>(attp, lsum, att);

    // 9: out proj (fp32 output)
    gemm_f16<false><<<dim3(DIM_ / 128, BNQ / 128), 256, GEMM_SMEM>>>(
        att, woT, out, DIM_, INNER_, 1.f);
}

// round 13
// speedup vs baseline: 1.0083x; 1.0083x over previous
#include <cuda_runtime.h>
#include <cuda_fp16.h>
#include <cstdint>

// ---------------- problem constants ----------------
#define BB     8
#define NQ_    256
#define DIM_   768
#define KVD_   1024
#define HH     8
#define DH_    64
#define INNER_ 512
#define TM_    8192
#define BNQ    2048
#define BTM    65536
#define LN_EPS 1e-5f

// q scale folded with log2(e): 0.125 * 1.4426950408889634
#define QSCALE 0.18033688011112043f

#define NSPLIT 2
#define KVSPLIT (TM_ / NSPLIT)              // 4096

// ---------------- scratch (device globals) ----------------
__device__ __half g_xn[BNQ * DIM_];
__device__ __half g_kvn[(size_t)BTM * KVD_];
__device__ __half g_wqT[INNER_ * DIM_];
__device__ __half g_wkvT[1024 * KVD_];
__device__ __half g_woT[DIM_ * INNER_];
__device__ __half g_qbuf[BNQ * INNER_];
__device__ __half g_kvp[(size_t)BTM * 1024];
__device__ __half g_att[BNQ * INNER_];
__device__ float  g_attp[NSPLIT * BNQ * INNER_];   // partial unnormalized O
__device__ float  g_lsum[NSPLIT * BNQ * HH];       // partial row sums

// ---------------- helpers ----------------
__device__ __forceinline__ uint32_t packh2(float lo, float hi) {
    uint32_t r;
    asm("cvt.rn.f16x2.f32 %0, %1, %2;" : "=r"(r) : "f"(hi), "f"(lo));
    return r;
}

__device__ __forceinline__ uint32_t h2e2(uint32_t x) {
    __half2 h = *reinterpret_cast<__half2*>(&x);
    h = h2exp2(h);
    return *reinterpret_cast<uint32_t*>(&h);
}

__device__ __forceinline__ float2 h22f2(uint32_t x) {
    __half2 h = *reinterpret_cast<__half2*>(&x);
    return __half22float2(h);
}

__device__ __forceinline__ void mma16(float c[4], const uint32_t a[4],
                                      uint32_t b0, uint32_t b1) {
    asm volatile("mma.sync.aligned.m16n8k16.row.col.f32.f16.f16.f32 "
        "{%0,%1,%2,%3}, {%4,%5,%6,%7}, {%8,%9}, {%0,%1,%2,%3};"
        : "+f"(c[0]), "+f"(c[1]), "+f"(c[2]), "+f"(c[3])
        : "r"(a[0]), "r"(a[1]), "r"(a[2]), "r"(a[3]), "r"(b0), "r"(b1));
}

__device__ __forceinline__ void cpa(uint32_t dst, const void* src) {
    asm volatile("cp.async.cg.shared.global [%0], [%1], 16;" :: "r"(dst), "l"(src));
}
#define CP_COMMIT asm volatile("cp.async.commit_group;")
#define CP_WAIT1  asm volatile("cp.async.wait_group 1;")
#define CP_WAIT2  asm volatile("cp.async.wait_group 2;")

__device__ __forceinline__ uint32_t smem_u32(const void* p) {
    return (uint32_t)__cvta_generic_to_shared(p);
}

#define LDSM_X4(r0, r1, r2, r3, addr) \
    asm volatile("ldmatrix.sync.aligned.m8n8.x4.shared.b16 {%0,%1,%2,%3}, [%4];" \
                 : "=r"(r0), "=r"(r1), "=r"(r2), "=r"(r3) : "r"(addr))
#define LDSM_T(r0, r1, r2, r3, addr) \
    asm volatile("ldmatrix.sync.aligned.m8n8.x4.trans.shared.b16 {%0,%1,%2,%3}, [%4];" \
                 : "=r"(r0), "=r"(r1), "=r"(r2), "=r"(r3) : "r"(addr))

// ---------------- fused LayerNorm + fp16 convert ----------------
template <int RL>
__global__ __launch_bounds__(256) void ln_conv(const float* __restrict__ X,
                                               const float* __restrict__ gam,
                                               const float* __restrict__ bet,
                                               __half* __restrict__ Y) {
    const int row = blockIdx.x;
    const int i = threadIdx.x;
    const bool act = i < RL / 4;
    float4 v = make_float4(0.f, 0.f, 0.f, 0.f);
    if (act) v = reinterpret_cast<const float4*>(X + (size_t)row * RL)[i];
    float s  = (v.x + v.y) + (v.z + v.w);
    float ss = v.x * v.x + v.y * v.y + v.z * v.z + v.w * v.w;
    #pragma unroll
    for (int o = 16; o; o >>= 1) {
        s  += __shfl_xor_sync(0xffffffffu, s, o);
        ss += __shfl_xor_sync(0xffffffffu, ss, o);
    }
    __shared__ float sh[16];
    __shared__ float st[2];
    const int w = i >> 5, l = i & 31;
    if (l == 0) { sh[w] = s; sh[w + 8] = ss; }
    __syncthreads();
    if (i == 0) {
        float S = 0.f, SS = 0.f;
        #pragma unroll
        for (int k = 0; k < 8; k++) { S += sh[k]; SS += sh[k + 8]; }
        const float m = S / (float)RL;
        st[0] = m;
        st[1] = rsqrtf(SS / (float)RL - m * m + LN_EPS);
    }
    __syncthreads();
    if (act) {
        const float m = st[0], r = st[1];
        const float4 gv = reinterpret_cast<const float4*>(gam)[i];
        const float4 bv = reinterpret_cast<const float4*>(bet)[i];
        uint2 o;
        o.x = packh2((v.x - m) * r * gv.x + bv.x, (v.y - m) * r * gv.y + bv.y);
        o.y = packh2((v.z - m) * r * gv.z + bv.z, (v.w - m) * r * gv.w + bv.w);
        *reinterpret_cast<uint2*>(Y + (size_t)row * RL + i * 4) = o;
    }
}

// ---------------- weight transpose ----------------
__global__ __launch_bounds__(256) void wconvT(const float* __restrict__ W,
                                              __half* __restrict__ Wt,
                                              int K, int N) {
    __shared__ __half t[32][33];
    const int tx = threadIdx.x, ty = threadIdx.y;
    const int k0 = blockIdx.y * 32, n0 = blockIdx.x * 32;
    #pragma unroll
    for (int i = 0; i < 4; i++)
        t[ty + i * 8][tx] = __float2half_rn(W[(size_t)(k0 + ty + i * 8) * N + n0 + tx]);
    __syncthreads();
    #pragma unroll
    for (int i = 0; i < 4; i++)
        Wt[(size_t)(n0 + ty + i * 8) * K + k0 + tx] = t[tx][ty + i * 8];
}

// ====== BIG GEMM: 256x128 CTA, 512 threads (16 warps as 8x2, 32x64 each), ======
// ====== BK=32, 4-stage, prefetch mid-compute, single sync per k-tile ===========
#define SAH 40
#define BG_A_H (256 * SAH)
#define BG_B_H (128 * SAH)
#define BG_STG_H (BG_A_H + BG_B_H)
#define BG_SMEM (4 * BG_STG_H * 2)          // 122880 B

__global__ __launch_bounds__(512, 1) void gemm_f16_big(
    const __half* __restrict__ A, const __half* __restrict__ Bt,
    __half* __restrict__ C, int N, int K) {
    extern __shared__ __half smh[];
    const uint32_t s_b = smem_u32(smh);

    const int tid = threadIdx.x;
    const int warp = tid >> 5, lane = tid & 31;
    const int g = lane >> 2, q = lane & 3;
    const int wm = (warp >> 1) * 32;
    const int wn = (warp & 1) * 64;
    const int bm0 = blockIdx.y * 256;
    const int bn0 = blockIdx.x * 128;
    const __half* Ab = A + (size_t)bm0 * K;
    const __half* Bb = Bt + (size_t)bn0 * K;

    const int lmA = (lane & 15) * SAH + ((lane >> 4) << 3);
    const int lmB = (((lane >> 4) << 3) + (lane & 7)) * SAH + (((lane >> 3) & 1) << 3);

    auto issue = [&](int stage, int kt) {
        const uint32_t base = s_b + stage * BG_STG_H * 2;
        #pragma unroll
        for (int c = 0; c < 2; c++) {
            const int cid = tid + c * 512;
            const int row = cid >> 2, c8 = (cid & 3) * 8;
            cpa(base + (uint32_t)(row * SAH + c8) * 2,
                Ab + (size_t)row * K + kt + c8);
        }
        {
            const int row = tid >> 2, c8 = (tid & 3) * 8;
            cpa(base + BG_A_H * 2 + (uint32_t)(row * SAH + c8) * 2,
                Bb + (size_t)row * K + kt + c8);
        }
    };

    float acc[2][8][4];
    #pragma unroll
    for (int mt = 0; mt < 2; mt++)
        #pragma unroll
        for (int nt = 0; nt < 8; nt++)
            #pragma unroll
            for (int i = 0; i < 4; i++) acc[mt][nt][i] = 0.f;

    const int nk = K / 32;
    issue(0, 0);  CP_COMMIT;
    issue(1, 32); CP_COMMIT;
    issue(2, 64); CP_COMMIT;

    for (int t = 0; t < nk; t++) {
        CP_WAIT2;
        __syncthreads();
        const uint32_t cAb = s_b + ((t & 3) * BG_STG_H) * 2;
        const uint32_t cBb = cAb + BG_A_H * 2;
        #pragma unroll
        for (int kk = 0; kk < 32; kk += 16) {
            uint32_t af[2][4];
            #pragma unroll
            for (int mt = 0; mt < 2; mt++)
                LDSM_X4(af[mt][0], af[mt][1], af[mt][2], af[mt][3],
                        cAb + (uint32_t)((wm + mt * 16) * SAH + kk + lmA) * 2);
            #pragma unroll
            for (int p = 0; p < 4; p++) {
                uint32_t b0, b1, b2, b3;
                LDSM_X4(b0, b1, b2, b3,
                        cBb + (uint32_t)((wn + p * 16) * SAH + kk + lmB) * 2);
                mma16(acc[0][2 * p],     af[0], b0, b1);
                mma16(acc[1][2 * p],     af[1], b0, b1);
                mma16(acc[0][2 * p + 1], af[0], b2, b3);
                mma16(acc[1][2 * p + 1], af[1], b2, b3);
            }
            // prefetch between the two kk-halves: first HMMA chain already
            // in flight, loads get ~1/2 k-tile extra shadow
            if (kk == 0) {
                if (t + 3 < nk) issue((t + 3) & 3, (t + 3) * 32);
                CP_COMMIT;
            }
        }
    }

    #pragma unroll
    for (int mt = 0; mt < 2; mt++)
        #pragma unroll
        for (int nt = 0; nt < 8; nt++) {
            const int r0 = bm0 + wm + mt * 16 + g;
            const int c0 = bn0 + wn + nt * 8 + 2 * q;
            *reinterpret_cast<uint32_t*>(C + (size_t)r0 * N + c0) =
                packh2(acc[mt][nt][0], acc[mt][nt][1]);
            *reinterpret_cast<uint32_t*>(C + (size_t)(r0 + 8) * N + c0) =
                packh2(acc[mt][nt][2], acc[mt][nt][3]);
        }
}

// ---------------- small pipelined fp16 GEMM (128x128x32, 3-stage) ----------------
#define ASTG_H (128 * SAH)
#define STAGE_H (2 * ASTG_H)
#define GEMM_SMEM (3 * STAGE_H * 2)   // 61440 B

template <bool OTF>
__global__ __launch_bounds__(256, 2) void gemm_f16(
    const __half* __restrict__ A, const __half* __restrict__ Bt,
    void* __restrict__ Cv, int N, int K, float alpha) {
    extern __shared__ __half smh[];
    const uint32_t s_b = smem_u32(smh);

    const int tid = threadIdx.x;
    const int warp = tid >> 5, lane = tid & 31;
    const int g = lane >> 2, q = lane & 3;
    const int wm = (warp >> 1) * 32;
    const int wn = (warp & 1) * 64;
    const int bm0 = blockIdx.y * 128;
    const int bn0 = blockIdx.x * 128;
    const __half* Ab = A + (size_t)bm0 * K;
    const __half* Bb = Bt + (size_t)bn0 * K;

    const int lmA = (lane & 15) * SAH + ((lane >> 4) << 3);
    const int lmB = (((lane >> 4) << 3) + (lane & 7)) * SAH + (((lane >> 3) & 1) << 3);

    auto issue = [&](int stage, int kt) {
        const uint32_t base = s_b + stage * STAGE_H * 2;
        #pragma unroll
        for (int c = 0; c < 2; c++) {
            const int cid = tid + c * 256;
            const int row = cid >> 2, c8 = (cid & 3) * 8;
            cpa(base + (uint32_t)(row * SAH + c8) * 2,
                Ab + (size_t)row * K + kt + c8);
            cpa(base + ASTG_H * 2 + (uint32_t)(row * SAH + c8) * 2,
                Bb + (size_t)row * K + kt + c8);
        }
    };

    float acc[2][8][4];
    #pragma unroll
    for (int mt = 0; mt < 2; mt++)
        #pragma unroll
        for (int nt = 0; nt < 8; nt++)
            #pragma unroll
            for (int i = 0; i < 4; i++) acc[mt][nt][i] = 0.f;

    const int nk = K / 32;
    issue(0, 0);  CP_COMMIT;
    issue(1, 32); CP_COMMIT;

    for (int t = 0; t < nk; t++) {
        if (t + 2 < nk) issue((t + 2) % 3, (t + 2) * 32);
        CP_COMMIT;
        CP_WAIT2;
        __syncthreads();
        const uint32_t cAb = s_b + ((t % 3) * STAGE_H) * 2;
        const uint32_t cBb = cAb + ASTG_H * 2;
        #pragma unroll
        for (int kk = 0; kk < 32; kk += 16) {
            uint32_t af[2][4];
            #pragma unroll
            for (int mt = 0; mt < 2; mt++)
                LDSM_X4(af[mt][0], af[mt][1], af[mt][2], af[mt][3],
                        cAb + (uint32_t)((wm + mt * 16) * SAH + kk + lmA) * 2);
            #pragma unroll
            for (int p = 0; p < 4; p++) {
                uint32_t b0, b1, b2, b3;
                LDSM_X4(b0, b1, b2, b3,
                        cBb + (uint32_t)((wn + p * 16) * SAH + kk + lmB) * 2);
                mma16(acc[0][2 * p],     af[0], b0, b1);
                mma16(acc[1][2 * p],     af[1], b0, b1);
                mma16(acc[0][2 * p + 1], af[0], b2, b3);
                mma16(acc[1][2 * p + 1], af[1], b2, b3);
            }
        }
        __syncthreads();
    }

    #pragma unroll
    for (int mt = 0; mt < 2; mt++)
        #pragma unroll
        for (int nt = 0; nt < 8; nt++) {
            const int r0 = bm0 + wm + mt * 16 + g;
            const int c0 = bn0 + wn + nt * 8 + 2 * q;
            if (OTF) {
                __half* C = (__half*)Cv;
                *reinterpret_cast<uint32_t*>(C + (size_t)r0 * N + c0) =
                    packh2(acc[mt][nt][0] * alpha, acc[mt][nt][1] * alpha);
                *reinterpret_cast<uint32_t*>(C + (size_t)(r0 + 8) * N + c0) =
                    packh2(acc[mt][nt][2] * alpha, acc[mt][nt][3] * alpha);
            } else {
                float* C = (float*)Cv;
                *reinterpret_cast<float2*>(C + (size_t)r0 * N + c0) =
                    make_float2(acc[mt][nt][0] * alpha, acc[mt][nt][1] * alpha);
                *reinterpret_cast<float2*>(C + (size_t)(r0 + 8) * N + c0) =
                    make_float2(acc[mt][nt][2] * alpha, acc[mt][nt][3] * alpha);
            }
        }
}

// ---------------- flash attention: Q-tile 256, KV-split 2, partial outputs ----
#define JC   64
#define KST  88
#define TILE_H (JC * KST)
#define KOFF(buf) ((buf) * TILE_H)
#define VOFF(buf) (2 * TILE_H + (buf) * TILE_H)
#define ATT_SMEM (4 * TILE_H * 2)

__global__ __launch_bounds__(256, 1) void attention_kernel(
    const __half* __restrict__ Q, const __half* __restrict__ KV,
    float* __restrict__ Op, float* __restrict__ Lp) {
    extern __shared__ __half smh[];
    const uint32_t s_b = smem_u32(smh);

    const int bh = blockIdx.x;
    const int b = bh >> 3, h = bh & 7;
    const int split = blockIdx.y;
    const int tid = threadIdx.x, warp = tid >> 5, lane = tid & 31;
    const int g = lane >> 2, q = lane & 3;

    const __half* Kg = KV + ((size_t)(b * TM_) + split * KVSPLIT) * 1024 + h * DH_;
    const __half* Vg = Kg + INNER_;

    auto issue = [&](int buf, int j0) {
        #pragma unroll
        for (int p = 0; p < 2; p++) {
            const int cid = tid + p * 256;
            const int jj = cid >> 3, c8 = (cid & 7) * 8;
            cpa(s_b + (uint32_t)(KOFF(buf) + jj * KST + c8) * 2,
                Kg + (size_t)(j0 + jj) * 1024 + c8);
            cpa(s_b + (uint32_t)(VOFF(buf) + jj * KST + c8) * 2,
                Vg + (size_t)(j0 + jj) * 1024 + c8);
        }
    };

    const int qrow0 = b * NQ_ + warp * 32;
    uint32_t qa[2][4][4];
    #pragma unroll
    for (int mt = 0; mt < 2; mt++) {
        const __half* Qb = Q + (size_t)(qrow0 + mt * 16) * INNER_ + h * DH_;
        #pragma unroll
        for (int ks = 0; ks < 4; ks++) {
            const __half* p = Qb + (size_t)g * INNER_ + ks * 16 + 2 * q;
            qa[mt][ks][0] = *reinterpret_cast<const uint32_t*>(p);
            qa[mt][ks][1] = *reinterpret_cast<const uint32_t*>(p + 8 * INNER_);
            qa[mt][ks][2] = *reinterpret_cast<const uint32_t*>(p + 8);
            qa[mt][ks][3] = *reinterpret_cast<const uint32_t*>(p + 8 * INNER_ + 8);
        }
    }

    float oacc[2][8][4];
    #pragma unroll
    for (int mt = 0; mt < 2; mt++)
        #pragma unroll
        for (int nt = 0; nt < 8; nt++)
            #pragma unroll
            for (int i = 0; i < 4; i++) oacc[mt][nt][i] = 0.f;
    float lr[2][2] = {{0.f, 0.f}, {0.f, 0.f}};

    const int lmB = (((lane >> 4) << 3) + (lane & 7)) * KST + (((lane >> 3) & 1) << 3);
    const int lm_row = lane & 15;
    const int lm_col = (lane >> 4) * 8;

    const int NC = KVSPLIT / JC;
    issue(0, 0); CP_COMMIT;

    for (int jc = 0; jc < NC; jc++) {
        const int buf = jc & 1;
        if (jc + 1 < NC) issue(buf ^ 1, (jc + 1) * JC);
        CP_COMMIT;
        CP_WAIT1;
        __syncthreads();

        float sacc[2][8][4];
        #pragma unroll
        for (int mt = 0; mt < 2; mt++)
            #pragma unroll
            for (int nt = 0; nt < 8; nt++)
                #pragma unroll
                for (int i = 0; i < 4; i++) sacc[mt][nt][i] = 0.f;
        const uint32_t kb = s_b + (uint32_t)KOFF(buf) * 2;
        #pragma unroll
        for (int ks = 0; ks < 4; ks++) {
            #pragma unroll
            for (int p = 0; p < 4; p++) {
                uint32_t b0, b1, b2, b3;
                LDSM_X4(b0, b1, b2, b3,
                        kb + (uint32_t)(p * 16 * KST + ks * 16 + lmB) * 2);
                #pragma unroll
                for (int mt = 0; mt < 2; mt++) {
                    mma16(sacc[mt][2 * p],     qa[mt][ks], b0, b1);
                    mma16(sacc[mt][2 * p + 1], qa[mt][ks], b2, b3);
                }
            }
        }

        uint32_t pa[2][4][4];
        #pragma unroll
        for (int mt = 0; mt < 2; mt++) {
            float ls0 = 0.f, ls1 = 0.f;
            #pragma unroll
            for (int ks = 0; ks < 4; ks++) {
                pa[mt][ks][0] = h2e2(packh2(sacc[mt][2 * ks][0],     sacc[mt][2 * ks][1]));
                pa[mt][ks][1] = h2e2(packh2(sacc[mt][2 * ks][2],     sacc[mt][2 * ks][3]));
                pa[mt][ks][2] = h2e2(packh2(sacc[mt][2 * ks + 1][0], sacc[mt][2 * ks + 1][1]));
                pa[mt][ks][3] = h2e2(packh2(sacc[mt][2 * ks + 1][2], sacc[mt][2 * ks + 1][3]));
                float2 a0 = h22f2(pa[mt][ks][0]), a2 = h22f2(pa[mt][ks][2]);
                ls0 += (a0.x + a0.y) + (a2.x + a2.y);
                float2 a1 = h22f2(pa[mt][ks][1]), a3 = h22f2(pa[mt][ks][3]);
                ls1 += (a1.x + a1.y) + (a3.x + a3.y);
            }
            lr[mt][0] += ls0;
            lr[mt][1] += ls1;
        }

        const uint32_t vbase =
            s_b + (uint32_t)(VOFF(buf) + lm_row * KST + lm_col) * 2;
        #pragma unroll
        for (int ks = 0; ks < 4; ks++) {
            #pragma unroll
            for (int dg = 0; dg < 4; dg++) {
                uint32_t v0, v1, v2, v3;
                LDSM_T(v0, v1, v2, v3,
                       vbase + (uint32_t)(ks * 16 * KST + dg * 16) * 2);
                #pragma unroll
                for (int mt = 0; mt < 2; mt++) {
                    mma16(oacc[mt][dg * 2],     pa[mt][ks], v0, v1);
                    mma16(oacc[mt][dg * 2 + 1], pa[mt][ks], v2, v3);
                }
            }
        }
        __syncthreads();
    }

    float* Ob = Op + (size_t)split * BNQ * INNER_;
    #pragma unroll
    for (int mt = 0; mt < 2; mt++) {
        const int r0 = qrow0 + mt * 16 + g;
        #pragma unroll
        for (int nt = 0; nt < 8; nt++) {
            const int c0 = h * DH_ + nt * 8 + 2 * q;
            *reinterpret_cast<float2*>(Ob + (size_t)r0 * INNER_ + c0) =
                make_float2(oacc[mt][nt][0], oacc[mt][nt][1]);
            *reinterpret_cast<float2*>(Ob + (size_t)(r0 + 8) * INNER_ + c0) =
                make_float2(oacc[mt][nt][2], oacc[mt][nt][3]);
        }
        float l0 = lr[mt][0], l1 = lr[mt][1];
        #pragma unroll
        for (int o = 1; o < 4; o <<= 1) {
            l0 += __shfl_xor_sync(0xffffffffu, l0, o);
            l1 += __shfl_xor_sync(0xffffffffu, l1, o);
        }
        if (q == 0) {
            Lp[((size_t)split * BNQ + r0) * HH + h]     = l0;
            Lp[((size_t)split * BNQ + r0 + 8) * HH + h] = l1;
        }
    }
}

// ---------------- attention reduce: att = sum(Oi)/sum(li), fp16 ----------------
__global__ __launch_bounds__(256) void att_reduce(
    const float* __restrict__ Op, const float* __restrict__ Lp,
    __half* __restrict__ att) {
    const int r = blockIdx.x;
    const int c = threadIdx.x * 2;
    const int h = c >> 6;
    float ax = 0.f, ay = 0.f, l = 0.f;
    #pragma unroll
    for (int s = 0; s < NSPLIT; s++) {
        const float2 a = *reinterpret_cast<const float2*>(
            Op + ((size_t)s * BNQ + r) * INNER_ + c);
        ax += a.x; ay += a.y;
        l += Lp[((size_t)s * BNQ + r) * HH + h];
    }
    const float inv = 1.f / l;
    *reinterpret_cast<uint32_t*>(att + (size_t)r * INNER_ + c) =
        packh2(ax * inv, ay * inv);
}

// ---------------- launch ----------------
extern "C" void kernel_launch(void* const* d_in, const int* in_sizes, int n_in,
                              void* d_out, int out_size) {
    const float* x    = (const float*)d_in[0];
    const float* k_v  = (const float*)d_in[1];
    const float* g_q  = (const float*)d_in[2];
    const float* b_q  = (const float*)d_in[3];
    const float* g_kv = (const float*)d_in[4];
    const float* b_kv = (const float*)d_in[5];
    const float* Wq   = (const float*)d_in[6];
    const float* Wkv  = (const float*)d_in[7];
    const float* Wo   = (const float*)d_in[8];
    float* out = (float*)d_out;

    __half *xn, *kvn, *wqT, *wkvT, *woT, *qbuf, *kvp, *att;
    float *attp, *lsum;
    cudaGetSymbolAddress((void**)&xn,   g_xn);
    cudaGetSymbolAddress((void**)&kvn,  g_kvn);
    cudaGetSymbolAddress((void**)&wqT,  g_wqT);
    cudaGetSymbolAddress((void**)&wkvT, g_wkvT);
    cudaGetSymbolAddress((void**)&woT,  g_woT);
    cudaGetSymbolAddress((void**)&qbuf, g_qbuf);
    cudaGetSymbolAddress((void**)&kvp,  g_kvp);
    cudaGetSymbolAddress((void**)&att,  g_att);
    cudaGetSymbolAddress((void**)&attp, g_attp);
    cudaGetSymbolAddress((void**)&lsum, g_lsum);

    cudaFuncSetAttribute(gemm_f16<true>,
                         cudaFuncAttributeMaxDynamicSharedMemorySize, GEMM_SMEM);
    cudaFuncSetAttribute(gemm_f16<false>,
                         cudaFuncAttributeMaxDynamicSharedMemorySize, GEMM_SMEM);
    cudaFuncSetAttribute(gemm_f16_big,
                         cudaFuncAttributeMaxDynamicSharedMemorySize, BG_SMEM);
    cudaFuncSetAttribute(attention_kernel,
                         cudaFuncAttributeMaxDynamicSharedMemorySize, ATT_SMEM);

    // 0,1: LayerNorm + fp16 convert
    ln_conv<KVD_><<<BTM, 256>>>(k_v, g_kv, b_kv, kvn);
    ln_conv<DIM_><<<BNQ, 256>>>(x, g_q, b_q, xn);

    // 2: Wkv^T
    wconvT<<<dim3(1024 / 32, KVD_ / 32), dim3(32, 8)>>>(Wkv, wkvT, KVD_, 1024);

    // 3 (profiled slot): kv projection
    gemm_f16_big<<<dim3(1024 / 128, BTM / 256), 512, BG_SMEM>>>(
        kvn, wkvT, kvp, 1024, KVD_);

    // 4,5: independent weight transposes — PDL so they fill GEMM tail
    {
        cudaLaunchAttribute attr[1];
        attr[0].id = cudaLaunchAttributeProgrammaticStreamSerialization;
        attr[0].val.programmaticStreamSerializationAllowed = 1;

        cudaLaunchConfig_t cfg = {};
        cfg.blockDim = dim3(32, 8);
        cfg.dynamicSmemBytes = 0;
        cfg.stream = 0;
        cfg.attrs = attr;
        cfg.numAttrs = 1;

        cfg.gridDim = dim3(INNER_ / 32, DIM_ / 32);
        cudaLaunchKernelEx(&cfg, wconvT, Wq, wqT, DIM_, INNER_);
        cfg.gridDim = dim3(DIM_ / 32, INNER_ / 32);
        cudaLaunchKernelEx(&cfg, wconvT, Wo, woT, INNER_, DIM_);
    }

    // 6: q proj with exp2-folded scale
    gemm_f16<true><<<dim3(INNER_ / 128, BNQ / 128), 256, GEMM_SMEM>>>(
        xn, wqT, qbuf, INNER_, DIM_, QSCALE);

    // 7: flash attention (2-way KV split, partial outputs)
    attention_kernel<<<dim3(BB * HH, NSPLIT), 256, ATT_SMEM>>>(qbuf, kvp, attp, lsum);

    // 8: combine partials
    att_reduce<<<BNQ, 256>>>(attp, lsum, att);

    // 9: out proj (fp32 output)
    gemm_f16<false><<<dim3(DIM_ / 128, BNQ / 128), 256, GEMM_SMEM>>>(
        att, woT, out, DIM_, INNER_, 1.f);
}

// round 15
// speedup vs baseline: 1.0249x; 1.0165x over previous
#include <cuda_runtime.h>
#include <cuda_fp16.h>
#include <cstdint>

// ---------------- problem constants ----------------
#define BB     8
#define NQ_    256
#define DIM_   768
#define KVD_   1024
#define HH     8
#define DH_    64
#define INNER_ 512
#define TM_    8192
#define BNQ    2048
#define BTM    65536
#define LN_EPS 1e-5f

// q scale folded with log2(e): 0.125 * 1.4426950408889634
#define QSCALE 0.18033688011112043f

#define NSPLIT 2
#define KVSPLIT (TM_ / NSPLIT)              // 4096

// ---------------- scratch (device globals) ----------------
__device__ __half g_xn[BNQ * DIM_];
__device__ __half g_kvn[(size_t)BTM * KVD_];
__device__ __half g_wqT[INNER_ * DIM_];
__device__ __half g_wkvT[1024 * KVD_];
__device__ __half g_woT[DIM_ * INNER_];
__device__ __half g_qbuf[BNQ * INNER_];
__device__ __half g_kvp[(size_t)BTM * 1024];
__device__ __half g_att[BNQ * INNER_];
__device__ float  g_attp[NSPLIT * BNQ * INNER_];
__device__ float  g_lsum[NSPLIT * BNQ * HH];

// ---------------- helpers ----------------
__device__ __forceinline__ uint32_t packh2(float lo, float hi) {
    uint32_t r;
    asm("cvt.rn.f16x2.f32 %0, %1, %2;" : "=r"(r) : "f"(hi), "f"(lo));
    return r;
}

__device__ __forceinline__ uint32_t h2e2(uint32_t x) {
    __half2 h = *reinterpret_cast<__half2*>(&x);
    h = h2exp2(h);
    return *reinterpret_cast<uint32_t*>(&h);
}

__device__ __forceinline__ float2 h22f2(uint32_t x) {
    __half2 h = *reinterpret_cast<__half2*>(&x);
    return __half22float2(h);
}

__device__ __forceinline__ void mma16(float c[4], const uint32_t a[4],
                                      uint32_t b0, uint32_t b1) {
    asm volatile("mma.sync.aligned.m16n8k16.row.col.f32.f16.f16.f32 "
        "{%0,%1,%2,%3}, {%4,%5,%6,%7}, {%8,%9}, {%0,%1,%2,%3};"
        : "+f"(c[0]), "+f"(c[1]), "+f"(c[2]), "+f"(c[3])
        : "r"(a[0]), "r"(a[1]), "r"(a[2]), "r"(a[3]), "r"(b0), "r"(b1));
}

__device__ __forceinline__ void cpa(uint32_t dst, const void* src) {
    asm volatile("cp.async.cg.shared.global [%0], [%1], 16;" :: "r"(dst), "l"(src));
}
#define CP_COMMIT asm volatile("cp.async.commit_group;")
#define CP_WAIT1  asm volatile("cp.async.wait_group 1;")
#define CP_WAIT2  asm volatile("cp.async.wait_group 2;")

__device__ __forceinline__ uint32_t smem_u32(const void* p) {
    return (uint32_t)__cvta_generic_to_shared(p);
}

#define LDSM_X4(r0, r1, r2, r3, addr) \
    asm volatile("ldmatrix.sync.aligned.m8n8.x4.shared.b16 {%0,%1,%2,%3}, [%4];" \
                 : "=r"(r0), "=r"(r1), "=r"(r2), "=r"(r3) : "r"(addr))
#define LDSM_T(r0, r1, r2, r3, addr) \
    asm volatile("ldmatrix.sync.aligned.m8n8.x4.trans.shared.b16 {%0,%1,%2,%3}, [%4];" \
                 : "=r"(r0), "=r"(r1), "=r"(r2), "=r"(r3) : "r"(addr))

// ---------------- fused LayerNorm + fp16 convert ----------------
template <int RL>
__global__ __launch_bounds__(256) void ln_conv(const float* __restrict__ X,
                                               const float* __restrict__ gam,
                                               const float* __restrict__ bet,
                                               __half* __restrict__ Y) {
    const int row = blockIdx.x;
    const int i = threadIdx.x;
    const bool act = i < RL / 4;
    float4 v = make_float4(0.f, 0.f, 0.f, 0.f);
    if (act) v = reinterpret_cast<const float4*>(X + (size_t)row * RL)[i];
    float s  = (v.x + v.y) + (v.z + v.w);
    float ss = v.x * v.x + v.y * v.y + v.z * v.z + v.w * v.w;
    #pragma unroll
    for (int o = 16; o; o >>= 1) {
        s  += __shfl_xor_sync(0xffffffffu, s, o);
        ss += __shfl_xor_sync(0xffffffffu, ss, o);
    }
    __shared__ float sh[16];
    __shared__ float st[2];
    const int w = i >> 5, l = i & 31;
    if (l == 0) { sh[w] = s; sh[w + 8] = ss; }
    __syncthreads();
    if (i == 0) {
        float S = 0.f, SS = 0.f;
        #pragma unroll
        for (int k = 0; k < 8; k++) { S += sh[k]; SS += sh[k + 8]; }
        const float m = S / (float)RL;
        st[0] = m;
        st[1] = rsqrtf(SS / (float)RL - m * m + LN_EPS);
    }
    __syncthreads();
    if (act) {
        const float m = st[0], r = st[1];
        const float4 gv = reinterpret_cast<const float4*>(gam)[i];
        const float4 bv = reinterpret_cast<const float4*>(bet)[i];
        uint2 o;
        o.x = packh2((v.x - m) * r * gv.x + bv.x, (v.y - m) * r * gv.y + bv.y);
        o.y = packh2((v.z - m) * r * gv.z + bv.z, (v.w - m) * r * gv.w + bv.w);
        *reinterpret_cast<uint2*>(Y + (size_t)row * RL + i * 4) = o;
    }
}

// ---------------- weight transpose ----------------
__global__ __launch_bounds__(256) void wconvT(const float* __restrict__ W,
                                              __half* __restrict__ Wt,
                                              int K, int N) {
    __shared__ __half t[32][33];
    const int tx = threadIdx.x, ty = threadIdx.y;
    const int k0 = blockIdx.y * 32, n0 = blockIdx.x * 32;
    #pragma unroll
    for (int i = 0; i < 4; i++)
        t[ty + i * 8][tx] = __float2half_rn(W[(size_t)(k0 + ty + i * 8) * N + n0 + tx]);
    __syncthreads();
    #pragma unroll
    for (int i = 0; i < 4; i++)
        Wt[(size_t)(n0 + ty + i * 8) * K + k0 + tx] = t[tx][ty + i * 8];
}

// ====== BIG GEMM (exact R11): 256x128 CTA, 512 thr (16 warps, 32x64 each), ======
// ====== BK=32, 4-stage, single sync, prefetch after compute ====================
#define SAH 40
#define BG_A_H (256 * SAH)
#define BG_B_H (128 * SAH)
#define BG_STG_H (BG_A_H + BG_B_H)
#define BG_SMEM (4 * BG_STG_H * 2)          // 122880 B

__global__ __launch_bounds__(512, 1) void gemm_f16_big(
    const __half* __restrict__ A, const __half* __restrict__ Bt,
    __half* __restrict__ C, int N, int K) {
    extern __shared__ __half smh[];
    const uint32_t s_b = smem_u32(smh);

    const int tid = threadIdx.x;
    const int warp = tid >> 5, lane = tid & 31;
    const int g = lane >> 2, q = lane & 3;
    const int wm = (warp >> 1) * 32;
    const int wn = (warp & 1) * 64;
    const int bm0 = blockIdx.y * 256;
    const int bn0 = blockIdx.x * 128;
    const __half* Ab = A + (size_t)bm0 * K;
    const __half* Bb = Bt + (size_t)bn0 * K;

    const int lmA = (lane & 15) * SAH + ((lane >> 4) << 3);
    const int lmB = (((lane >> 4) << 3) + (lane & 7)) * SAH + (((lane >> 3) & 1) << 3);

    auto issue = [&](int stage, int kt) {
        const uint32_t base = s_b + stage * BG_STG_H * 2;
        #pragma unroll
        for (int c = 0; c < 2; c++) {
            const int cid = tid + c * 512;
            const int row = cid >> 2, c8 = (cid & 3) * 8;
            cpa(base + (uint32_t)(row * SAH + c8) * 2,
                Ab + (size_t)row * K + kt + c8);
        }
        {
            const int row = tid >> 2, c8 = (tid & 3) * 8;
            cpa(base + BG_A_H * 2 + (uint32_t)(row * SAH + c8) * 2,
                Bb + (size_t)row * K + kt + c8);
        }
    };

    float acc[2][8][4];
    #pragma unroll
    for (int mt = 0; mt < 2; mt++)
        #pragma unroll
        for (int nt = 0; nt < 8; nt++)
            #pragma unroll
            for (int i = 0; i < 4; i++) acc[mt][nt][i] = 0.f;

    const int nk = K / 32;
    issue(0, 0);  CP_COMMIT;
    issue(1, 32); CP_COMMIT;
    issue(2, 64); CP_COMMIT;

    for (int t = 0; t < nk; t++) {
        CP_WAIT2;
        __syncthreads();
        const uint32_t cAb = s_b + ((t & 3) * BG_STG_H) * 2;
        const uint32_t cBb = cAb + BG_A_H * 2;
        #pragma unroll
        for (int kk = 0; kk < 32; kk += 16) {
            uint32_t af[2][4];
            #pragma unroll
            for (int mt = 0; mt < 2; mt++)
                LDSM_X4(af[mt][0], af[mt][1], af[mt][2], af[mt][3],
                        cAb + (uint32_t)((wm + mt * 16) * SAH + kk + lmA) * 2);
            #pragma unroll
            for (int p = 0; p < 4; p++) {
                uint32_t b0, b1, b2, b3;
                LDSM_X4(b0, b1, b2, b3,
                        cBb + (uint32_t)((wn + p * 16) * SAH + kk + lmB) * 2);
                mma16(acc[0][2 * p],     af[0], b0, b1);
                mma16(acc[1][2 * p],     af[1], b0, b1);
                mma16(acc[0][2 * p + 1], af[0], b2, b3);
                mma16(acc[1][2 * p + 1], af[1], b2, b3);
            }
        }
        if (t + 3 < nk) issue((t + 3) & 3, (t + 3) * 32);
        CP_COMMIT;
    }

    #pragma unroll
    for (int mt = 0; mt < 2; mt++)
        #pragma unroll
        for (int nt = 0; nt < 8; nt++) {
            const int r0 = bm0 + wm + mt * 16 + g;
            const int c0 = bn0 + wn + nt * 8 + 2 * q;
            *reinterpret_cast<uint32_t*>(C + (size_t)r0 * N + c0) =
                packh2(acc[mt][nt][0], acc[mt][nt][1]);
            *reinterpret_cast<uint32_t*>(C + (size_t)(r0 + 8) * N + c0) =
                packh2(acc[mt][nt][2], acc[mt][nt][3]);
        }
}

// ---------------- small fp16 GEMM: 128x128x32, 4-stage, single sync ----------------
#define ASTG_H (128 * SAH)
#define STAGE_H (2 * ASTG_H)
#define GEMM_SMEM (4 * STAGE_H * 2)   // 81920 B

template <bool OTF>
__global__ __launch_bounds__(256, 2) void gemm_f16(
    const __half* __restrict__ A, const __half* __restrict__ Bt,
    void* __restrict__ Cv, int N, int K, float alpha) {
    extern __shared__ __half smh[];
    const uint32_t s_b = smem_u32(smh);

    const int tid = threadIdx.x;
    const int warp = tid >> 5, lane = tid & 31;
    const int g = lane >> 2, q = lane & 3;
    const int wm = (warp >> 1) * 32;
    const int wn = (warp & 1) * 64;
    const int bm0 = blockIdx.y * 128;
    const int bn0 = blockIdx.x * 128;
    const __half* Ab = A + (size_t)bm0 * K;
    const __half* Bb = Bt + (size_t)bn0 * K;

    const int lmA = (lane & 15) * SAH + ((lane >> 4) << 3);
    const int lmB = (((lane >> 4) << 3) + (lane & 7)) * SAH + (((lane >> 3) & 1) << 3);

    auto issue = [&](int stage, int kt) {
        const uint32_t base = s_b + stage * STAGE_H * 2;
        #pragma unroll
        for (int c = 0; c < 2; c++) {
            const int cid = tid + c * 256;
            const int row = cid >> 2, c8 = (cid & 3) * 8;
            cpa(base + (uint32_t)(row * SAH + c8) * 2,
                Ab + (size_t)row * K + kt + c8);
            cpa(base + ASTG_H * 2 + (uint32_t)(row * SAH + c8) * 2,
                Bb + (size_t)row * K + kt + c8);
        }
    };

    float acc[2][8][4];
    #pragma unroll
    for (int mt = 0; mt < 2; mt++)
        #pragma unroll
        for (int nt = 0; nt < 8; nt++)
            #pragma unroll
            for (int i = 0; i < 4; i++) acc[mt][nt][i] = 0.f;

    const int nk = K / 32;
    issue(0, 0);  CP_COMMIT;
    issue(1, 32); CP_COMMIT;
    issue(2, 64); CP_COMMIT;

    for (int t = 0; t < nk; t++) {
        CP_WAIT2;
        __syncthreads();
        const uint32_t cAb = s_b + ((t & 3) * STAGE_H) * 2;
        const uint32_t cBb = cAb + ASTG_H * 2;
        #pragma unroll
        for (int kk = 0; kk < 32; kk += 16) {
            uint32_t af[2][4];
            #pragma unroll
            for (int mt = 0; mt < 2; mt++)
                LDSM_X4(af[mt][0], af[mt][1], af[mt][2], af[mt][3],
                        cAb + (uint32_t)((wm + mt * 16) * SAH + kk + lmA) * 2);
            #pragma unroll
            for (int p = 0; p < 4; p++) {
                uint32_t b0, b1, b2, b3;
                LDSM_X4(b0, b1, b2, b3,
                        cBb + (uint32_t)((wn + p * 16) * SAH + kk + lmB) * 2);
                mma16(acc[0][2 * p],     af[0], b0, b1);
                mma16(acc[1][2 * p],     af[1], b0, b1);
                mma16(acc[0][2 * p + 1], af[0], b2, b3);
                mma16(acc[1][2 * p + 1], af[1], b2, b3);
            }
        }
        if (t + 3 < nk) issue((t + 3) & 3, (t + 3) * 32);
        CP_COMMIT;
    }

    #pragma unroll
    for (int mt = 0; mt < 2; mt++)
        #pragma unroll
        for (int nt = 0; nt < 8; nt++) {
            const int r0 = bm0 + wm + mt * 16 + g;
            const int c0 = bn0 + wn + nt * 8 + 2 * q;
            if (OTF) {
                __half* C = (__half*)Cv;
                *reinterpret_cast<uint32_t*>(C + (size_t)r0 * N + c0) =
                    packh2(acc[mt][nt][0] * alpha, acc[mt][nt][1] * alpha);
                *reinterpret_cast<uint32_t*>(C + (size_t)(r0 + 8) * N + c0) =
                    packh2(acc[mt][nt][2] * alpha, acc[mt][nt][3] * alpha);
            } else {
                float* C = (float*)Cv;
                *reinterpret_cast<float2*>(C + (size_t)r0 * N + c0) =
                    make_float2(acc[mt][nt][0] * alpha, acc[mt][nt][1] * alpha);
                *reinterpret_cast<float2*>(C + (size_t)(r0 + 8) * N + c0) =
                    make_float2(acc[mt][nt][2] * alpha, acc[mt][nt][3] * alpha);
            }
        }
}

// ---------------- flash attention: KV-split 2, 4-buffer ring, single sync ------
#define JC   64
#define KST  88
#define TILE_H (JC * KST)
#define KOFF(buf) ((buf) * TILE_H)
#define VOFF(buf) ((4 + (buf)) * TILE_H)
#define ATT_SMEM (8 * TILE_H * 2)           // 90112 B

__global__ __launch_bounds__(256, 1) void attention_kernel(
    const __half* __restrict__ Q, const __half* __restrict__ KV,
    float* __restrict__ Op, float* __restrict__ Lp) {
    extern __shared__ __half smh[];
    const uint32_t s_b = smem_u32(smh);

    const int bh = blockIdx.x;
    const int b = bh >> 3, h = bh & 7;
    const int split = blockIdx.y;
    const int tid = threadIdx.x, warp = tid >> 5, lane = tid & 31;
    const int g = lane >> 2, q = lane & 3;

    const __half* Kg = KV + ((size_t)(b * TM_) + split * KVSPLIT) * 1024 + h * DH_;
    const __half* Vg = Kg + INNER_;

    auto issue = [&](int buf, int j0) {
        #pragma unroll
        for (int p = 0; p < 2; p++) {
            const int cid = tid + p * 256;
            const int jj = cid >> 3, c8 = (cid & 7) * 8;
            cpa(s_b + (uint32_t)(KOFF(buf) + jj * KST + c8) * 2,
                Kg + (size_t)(j0 + jj) * 1024 + c8);
            cpa(s_b + (uint32_t)(VOFF(buf) + jj * KST + c8) * 2,
                Vg + (size_t)(j0 + jj) * 1024 + c8);
        }
    };

    const int qrow0 = b * NQ_ + warp * 32;
    uint32_t qa[2][4][4];
    #pragma unroll
    for (int mt = 0; mt < 2; mt++) {
        const __half* Qb = Q + (size_t)(qrow0 + mt * 16) * INNER_ + h * DH_;
        #pragma unroll
        for (int ks = 0; ks < 4; ks++) {
            const __half* p = Qb + (size_t)g * INNER_ + ks * 16 + 2 * q;
            qa[mt][ks][0] = *reinterpret_cast<const uint32_t*>(p);
            qa[mt][ks][1] = *reinterpret_cast<const uint32_t*>(p + 8 * INNER_);
            qa[mt][ks][2] = *reinterpret_cast<const uint32_t*>(p + 8);
            qa[mt][ks][3] = *reinterpret_cast<const uint32_t*>(p + 8 * INNER_ + 8);
        }
    }

    float oacc[2][8][4];
    #pragma unroll
    for (int mt = 0; mt < 2; mt++)
        #pragma unroll
        for (int nt = 0; nt < 8; nt++)
            #pragma unroll
            for (int i = 0; i < 4; i++) oacc[mt][nt][i] = 0.f;
    float lr[2][2] = {{0.f, 0.f}, {0.f, 0.f}};

    const int lmB = (((lane >> 4) << 3) + (lane & 7)) * KST + (((lane >> 3) & 1) << 3);
    const int lm_row = lane & 15;
    const int lm_col = (lane >> 4) * 8;

    const int NC = KVSPLIT / JC;
    issue(0, 0); CP_COMMIT;

    for (int jc = 0; jc < NC; jc++) {
        const int buf = jc & 3;
        if (jc + 1 < NC) issue((jc + 1) & 3, (jc + 1) * JC);
        CP_COMMIT;
        CP_WAIT1;
        __syncthreads();

        float sacc[2][8][4];
        #pragma unroll
        for (int mt = 0; mt < 2; mt++)
            #pragma unroll
            for (int nt = 0; nt < 8; nt++)
                #pragma unroll
                for (int i = 0; i < 4; i++) sacc[mt][nt][i] = 0.f;
        const uint32_t kb = s_b + (uint32_t)KOFF(buf) * 2;
        #pragma unroll
        for (int ks = 0; ks < 4; ks++) {
            #pragma unroll
            for (int p = 0; p < 4; p++) {
                uint32_t b0, b1, b2, b3;
                LDSM_X4(b0, b1, b2, b3,
                        kb + (uint32_t)(p * 16 * KST + ks * 16 + lmB) * 2);
                #pragma unroll
                for (int mt = 0; mt < 2; mt++) {
                    mma16(sacc[mt][2 * p],     qa[mt][ks], b0, b1);
                    mma16(sacc[mt][2 * p + 1], qa[mt][ks], b2, b3);
                }
            }
        }

        uint32_t pa[2][4][4];
        #pragma unroll
        for (int mt = 0; mt < 2; mt++) {
            float ls0 = 0.f, ls1 = 0.f;
            #pragma unroll
            for (int ks = 0; ks < 4; ks++) {
                pa[mt][ks][0] = h2e2(packh2(sacc[mt][2 * ks][0],     sacc[mt][2 * ks][1]));
                pa[mt][ks][1] = h2e2(packh2(sacc[mt][2 * ks][2],     sacc[mt][2 * ks][3]));
                pa[mt][ks][2] = h2e2(packh2(sacc[mt][2 * ks + 1][0], sacc[mt][2 * ks + 1][1]));
                pa[mt][ks][3] = h2e2(packh2(sacc[mt][2 * ks + 1][2], sacc[mt][2 * ks + 1][3]));
                float2 a0 = h22f2(pa[mt][ks][0]), a2 = h22f2(pa[mt][ks][2]);
                ls0 += (a0.x + a0.y) + (a2.x + a2.y);
                float2 a1 = h22f2(pa[mt][ks][1]), a3 = h22f2(pa[mt][ks][3]);
                ls1 += (a1.x + a1.y) + (a3.x + a3.y);
            }
            lr[mt][0] += ls0;
            lr[mt][1] += ls1;
        }

        const uint32_t vbase =
            s_b + (uint32_t)(VOFF(buf) + lm_row * KST + lm_col) * 2;
        #pragma unroll
        for (int ks = 0; ks < 4; ks++) {
            #pragma unroll
            for (int dg = 0; dg < 4; dg++) {
                uint32_t v0, v1, v2, v3;
                LDSM_T(v0, v1, v2, v3,
                       vbase + (uint32_t)(ks * 16 * KST + dg * 16) * 2);
                #pragma unroll
                for (int mt = 0; mt < 2; mt++) {
                    mma16(oacc[mt][dg * 2],     pa[mt][ks], v0, v1);
                    mma16(oacc[mt][dg * 2 + 1], pa[mt][ks], v2, v3);
                }
            }
        }
        // no trailing sync: 4-buffer ring + per-iteration head barrier bound
        // warp skew to 1 iteration, so prefetch target (jc+1)&3 can't collide
    }

    float* Ob = Op + (size_t)split * BNQ * INNER_;
    #pragma unroll
    for (int mt = 0; mt < 2; mt++) {
        const int r0 = qrow0 + mt * 16 + g;
        #pragma unroll
        for (int nt = 0; nt < 8; nt++) {
            const int c0 = h * DH_ + nt * 8 + 2 * q;
            *reinterpret_cast<float2*>(Ob + (size_t)r0 * INNER_ + c0) =
                make_float2(oacc[mt][nt][0], oacc[mt][nt][1]);
            *reinterpret_cast<float2*>(Ob + (size_t)(r0 + 8) * INNER_ + c0) =
                make_float2(oacc[mt][nt][2], oacc[mt][nt][3]);
        }
        float l0 = lr[mt][0], l1 = lr[mt][1];
        #pragma unroll
        for (int o = 1; o < 4; o <<= 1) {
            l0 += __shfl_xor_sync(0xffffffffu, l0, o);
            l1 += __shfl_xor_sync(0xffffffffu, l1, o);
        }
        if (q == 0) {
            Lp[((size_t)split * BNQ + r0) * HH + h]     = l0;
            Lp[((size_t)split * BNQ + r0 + 8) * HH + h] = l1;
        }
    }
}

// ---------------- attention reduce ----------------
__global__ __launch_bounds__(256) void att_reduce(
    const float* __restrict__ Op, const float* __restrict__ Lp,
    __half* __restrict__ att) {
    const int r = blockIdx.x;
    const int c = threadIdx.x * 2;
    const int h = c >> 6;
    float ax = 0.f, ay = 0.f, l = 0.f;
    #pragma unroll
    for (int s = 0; s < NSPLIT; s++) {
        const float2 a = *reinterpret_cast<const float2*>(
            Op + ((size_t)s * BNQ + r) * INNER_ + c);
        ax += a.x; ay += a.y;
        l += Lp[((size_t)s * BNQ + r) * HH + h];
    }
    const float inv = 1.f / l;
    *reinterpret_cast<uint32_t*>(att + (size_t)r * INNER_ + c) =
        packh2(ax * inv, ay * inv);
}

// ---------------- launch ----------------
extern "C" void kernel_launch(void* const* d_in, const int* in_sizes, int n_in,
                              void* d_out, int out_size) {
    const float* x    = (const float*)d_in[0];
    const float* k_v  = (const float*)d_in[1];
    const float* g_q  = (const float*)d_in[2];
    const float* b_q  = (const float*)d_in[3];
    const float* g_kv = (const float*)d_in[4];
    const float* b_kv = (const float*)d_in[5];
    const float* Wq   = (const float*)d_in[6];
    const float* Wkv  = (const float*)d_in[7];
    const float* Wo   = (const float*)d_in[8];
    float* out = (float*)d_out;

    __half *xn, *kvn, *wqT, *wkvT, *woT, *qbuf, *kvp, *att;
    float *attp, *lsum;
    cudaGetSymbolAddress((void**)&xn,   g_xn);
    cudaGetSymbolAddress((void**)&kvn,  g_kvn);
    cudaGetSymbolAddress((void**)&wqT,  g_wqT);
    cudaGetSymbolAddress((void**)&wkvT, g_wkvT);
    cudaGetSymbolAddress((void**)&woT,  g_woT);
    cudaGetSymbolAddress((void**)&qbuf, g_qbuf);
    cudaGetSymbolAddress((void**)&kvp,  g_kvp);
    cudaGetSymbolAddress((void**)&att,  g_att);
    cudaGetSymbolAddress((void**)&attp, g_attp);
    cudaGetSymbolAddress((void**)&lsum, g_lsum);

    cudaFuncSetAttribute(gemm_f16<true>,
                         cudaFuncAttributeMaxDynamicSharedMemorySize, GEMM_SMEM);
    cudaFuncSetAttribute(gemm_f16<false>,
                         cudaFuncAttributeMaxDynamicSharedMemorySize, GEMM_SMEM);
    cudaFuncSetAttribute(gemm_f16_big,
                         cudaFuncAttributeMaxDynamicSharedMemorySize, BG_SMEM);
    cudaFuncSetAttribute(attention_kernel,
                         cudaFuncAttributeMaxDynamicSharedMemorySize, ATT_SMEM);

    // 0,1: LayerNorm + fp16 convert
    ln_conv<KVD_><<<BTM, 256>>>(k_v, g_kv, b_kv, kvn);
    ln_conv<DIM_><<<BNQ, 256>>>(x, g_q, b_q, xn);

    // 2: Wkv^T
    wconvT<<<dim3(1024 / 32, KVD_ / 32), dim3(32, 8)>>>(Wkv, wkvT, KVD_, 1024);

    // 3 (profiled slot): kv projection (R11 config)
    gemm_f16_big<<<dim3(1024 / 128, BTM / 256), 512, BG_SMEM>>>(
        kvn, wkvT, kvp, 1024, KVD_);

    // 4,5: remaining weight transposes
    wconvT<<<dim3(INNER_ / 32, DIM_ / 32), dim3(32, 8)>>>(Wq, wqT, DIM_, INNER_);
    wconvT<<<dim3(DIM_ / 32, INNER_ / 32), dim3(32, 8)>>>(Wo, woT, INNER_, DIM_);

    // 6: q proj with exp2-folded scale
    gemm_f16<true><<<dim3(INNER_ / 128, BNQ / 128), 256, GEMM_SMEM>>>(
        xn, wqT, qbuf, INNER_, DIM_, QSCALE);

    // 7: flash attention (2-way KV split, 4-buffer ring)
    attention_kernel<<<dim3(BB * HH, NSPLIT), 256, ATT_SMEM>>>(qbuf, kvp, attp, lsum);

    // 8: combine partials
    att_reduce<<<BNQ, 256>>>(attp, lsum, att);

    // 9: out proj (fp32 output)
    gemm_f16<false><<<dim3(DIM_ / 128, BNQ / 128), 256, GEMM_SMEM>>>(
        att, woT, out, DIM_, INNER_, 1.f);
}

// round 16
// speedup vs baseline: 1.0563x; 1.0306x over previous
#include <cuda_runtime.h>
#include <cuda_fp16.h>
#include <cstdint>

// ---------------- problem constants ----------------
#define BB     8
#define NQ_    256
#define DIM_   768
#define KVD_   1024
#define HH     8
#define DH_    64
#define INNER_ 512
#define TM_    8192
#define BNQ    2048
#define BTM    65536
#define LN_EPS 1e-5f

// q scale folded with log2(e): 0.125 * 1.4426950408889634
#define QSCALE 0.18033688011112043f

#define NSPLIT 2
#define KVSPLIT (TM_ / NSPLIT)              // 4096

// ---------------- scratch (device globals) ----------------
__device__ __half g_xn[BNQ * DIM_];
__device__ __half g_kvn[(size_t)BTM * KVD_];
__device__ __half g_wqT[INNER_ * DIM_];
__device__ __half g_wkvT[1024 * KVD_];
__device__ __half g_woT[DIM_ * INNER_];
__device__ __half g_qbuf[BNQ * INNER_];
__device__ __half g_kvp[(size_t)BTM * 1024];
__device__ __half g_att[BNQ * INNER_];
__device__ float  g_attp[NSPLIT * BNQ * INNER_];
__device__ float  g_lsum[NSPLIT * BNQ * HH];

// ---------------- helpers ----------------
__device__ __forceinline__ uint32_t packh2(float lo, float hi) {
    uint32_t r;
    asm("cvt.rn.f16x2.f32 %0, %1, %2;" : "=r"(r) : "f"(hi), "f"(lo));
    return r;
}

__device__ __forceinline__ uint32_t h2e2(uint32_t x) {
    __half2 h = *reinterpret_cast<__half2*>(&x);
    h = h2exp2(h);
    return *reinterpret_cast<uint32_t*>(&h);
}

__device__ __forceinline__ float2 h22f2(uint32_t x) {
    __half2 h = *reinterpret_cast<__half2*>(&x);
    return __half22float2(h);
}

__device__ __forceinline__ void mma16(float c[4], const uint32_t a[4],
                                      uint32_t b0, uint32_t b1) {
    asm volatile("mma.sync.aligned.m16n8k16.row.col.f32.f16.f16.f32 "
        "{%0,%1,%2,%3}, {%4,%5,%6,%7}, {%8,%9}, {%0,%1,%2,%3};"
        : "+f"(c[0]), "+f"(c[1]), "+f"(c[2]), "+f"(c[3])
        : "r"(a[0]), "r"(a[1]), "r"(a[2]), "r"(a[3]), "r"(b0), "r"(b1));
}

__device__ __forceinline__ void cpa(uint32_t dst, const void* src) {
    asm volatile("cp.async.cg.shared.global [%0], [%1], 16;" :: "r"(dst), "l"(src));
}
#define CP_COMMIT asm volatile("cp.async.commit_group;")
#define CP_WAIT1  asm volatile("cp.async.wait_group 1;")
#define CP_WAIT2  asm volatile("cp.async.wait_group 2;")

__device__ __forceinline__ uint32_t smem_u32(const void* p) {
    return (uint32_t)__cvta_generic_to_shared(p);
}

#define LDSM_X4(r0, r1, r2, r3, addr) \
    asm volatile("ldmatrix.sync.aligned.m8n8.x4.shared.b16 {%0,%1,%2,%3}, [%4];" \
                 : "=r"(r0), "=r"(r1), "=r"(r2), "=r"(r3) : "r"(addr))
#define LDSM_T(r0, r1, r2, r3, addr) \
    asm volatile("ldmatrix.sync.aligned.m8n8.x4.trans.shared.b16 {%0,%1,%2,%3}, [%4];" \
                 : "=r"(r0), "=r"(r1), "=r"(r2), "=r"(r3) : "r"(addr))

// ---------------- fused LayerNorm + fp16 convert ----------------
template <int RL>
__global__ __launch_bounds__(256) void ln_conv(const float* __restrict__ X,
                                               const float* __restrict__ gam,
                                               const float* __restrict__ bet,
                                               __half* __restrict__ Y) {
    const int row = blockIdx.x;
    const int i = threadIdx.x;
    const bool act = i < RL / 4;
    float4 v = make_float4(0.f, 0.f, 0.f, 0.f);
    if (act) v = reinterpret_cast<const float4*>(X + (size_t)row * RL)[i];
    float s  = (v.x + v.y) + (v.z + v.w);
    float ss = v.x * v.x + v.y * v.y + v.z * v.z + v.w * v.w;
    #pragma unroll
    for (int o = 16; o; o >>= 1) {
        s  += __shfl_xor_sync(0xffffffffu, s, o);
        ss += __shfl_xor_sync(0xffffffffu, ss, o);
    }
    __shared__ float sh[16];
    __shared__ float st[2];
    const int w = i >> 5, l = i & 31;
    if (l == 0) { sh[w] = s; sh[w + 8] = ss; }
    __syncthreads();
    if (i == 0) {
        float S = 0.f, SS = 0.f;
        #pragma unroll
        for (int k = 0; k < 8; k++) { S += sh[k]; SS += sh[k + 8]; }
        const float m = S / (float)RL;
        st[0] = m;
        st[1] = rsqrtf(SS / (float)RL - m * m + LN_EPS);
    }
    __syncthreads();
    if (act) {
        const float m = st[0], r = st[1];
        const float4 gv = reinterpret_cast<const float4*>(gam)[i];
        const float4 bv = reinterpret_cast<const float4*>(bet)[i];
        uint2 o;
        o.x = packh2((v.x - m) * r * gv.x + bv.x, (v.y - m) * r * gv.y + bv.y);
        o.y = packh2((v.z - m) * r * gv.z + bv.z, (v.w - m) * r * gv.w + bv.w);
        *reinterpret_cast<uint2*>(Y + (size_t)row * RL + i * 4) = o;
    }
}

// ---------------- weight transpose ----------------
__global__ __launch_bounds__(256) void wconvT(const float* __restrict__ W,
                                              __half* __restrict__ Wt,
                                              int K, int N) {
    __shared__ __half t[32][33];
    const int tx = threadIdx.x, ty = threadIdx.y;
    const int k0 = blockIdx.y * 32, n0 = blockIdx.x * 32;
    #pragma unroll
    for (int i = 0; i < 4; i++)
        t[ty + i * 8][tx] = __float2half_rn(W[(size_t)(k0 + ty + i * 8) * N + n0 + tx]);
    __syncthreads();
    #pragma unroll
    for (int i = 0; i < 4; i++)
        Wt[(size_t)(n0 + ty + i * 8) * K + k0 + tx] = t[tx][ty + i * 8];
}

// ====== BIG GEMM (exact R11): 256x128 CTA, 512 thr (16 warps, 32x64 each), ======
// ====== BK=32, 4-stage, single sync, prefetch after compute ====================
#define SAH 40
#define BG_A_H (256 * SAH)
#define BG_B_H (128 * SAH)
#define BG_STG_H (BG_A_H + BG_B_H)
#define BG_SMEM (4 * BG_STG_H * 2)          // 122880 B

__global__ __launch_bounds__(512, 1) void gemm_f16_big(
    const __half* __restrict__ A, const __half* __restrict__ Bt,
    __half* __restrict__ C, int N, int K) {
    extern __shared__ __half smh[];
    const uint32_t s_b = smem_u32(smh);

    const int tid = threadIdx.x;
    const int warp = tid >> 5, lane = tid & 31;
    const int g = lane >> 2, q = lane & 3;
    const int wm = (warp >> 1) * 32;
    const int wn = (warp & 1) * 64;
    const int bm0 = blockIdx.y * 256;
    const int bn0 = blockIdx.x * 128;
    const __half* Ab = A + (size_t)bm0 * K;
    const __half* Bb = Bt + (size_t)bn0 * K;

    const int lmA = (lane & 15) * SAH + ((lane >> 4) << 3);
    const int lmB = (((lane >> 4) << 3) + (lane & 7)) * SAH + (((lane >> 3) & 1) << 3);

    auto issue = [&](int stage, int kt) {
        const uint32_t base = s_b + stage * BG_STG_H * 2;
        #pragma unroll
        for (int c = 0; c < 2; c++) {
            const int cid = tid + c * 512;
            const int row = cid >> 2, c8 = (cid & 3) * 8;
            cpa(base + (uint32_t)(row * SAH + c8) * 2,
                Ab + (size_t)row * K + kt + c8);
        }
        {
            const int row = tid >> 2, c8 = (tid & 3) * 8;
            cpa(base + BG_A_H * 2 + (uint32_t)(row * SAH + c8) * 2,
                Bb + (size_t)row * K + kt + c8);
        }
    };

    float acc[2][8][4];
    #pragma unroll
    for (int mt = 0; mt < 2; mt++)
        #pragma unroll
        for (int nt = 0; nt < 8; nt++)
            #pragma unroll
            for (int i = 0; i < 4; i++) acc[mt][nt][i] = 0.f;

    const int nk = K / 32;
    issue(0, 0);  CP_COMMIT;
    issue(1, 32); CP_COMMIT;
    issue(2, 64); CP_COMMIT;

    for (int t = 0; t < nk; t++) {
        CP_WAIT2;
        __syncthreads();
        const uint32_t cAb = s_b + ((t & 3) * BG_STG_H) * 2;
        const uint32_t cBb = cAb + BG_A_H * 2;
        #pragma unroll
        for (int kk = 0; kk < 32; kk += 16) {
            uint32_t af[2][4];
            #pragma unroll
            for (int mt = 0; mt < 2; mt++)
                LDSM_X4(af[mt][0], af[mt][1], af[mt][2], af[mt][3],
                        cAb + (uint32_t)((wm + mt * 16) * SAH + kk + lmA) * 2);
            #pragma unroll
            for (int p = 0; p < 4; p++) {
                uint32_t b0, b1, b2, b3;
                LDSM_X4(b0, b1, b2, b3,
                        cBb + (uint32_t)((wn + p * 16) * SAH + kk + lmB) * 2);
                mma16(acc[0][2 * p],     af[0], b0, b1);
                mma16(acc[1][2 * p],     af[1], b0, b1);
                mma16(acc[0][2 * p + 1], af[0], b2, b3);
                mma16(acc[1][2 * p + 1], af[1], b2, b3);
            }
        }
        if (t + 3 < nk) issue((t + 3) & 3, (t + 3) * 32);
        CP_COMMIT;
    }

    #pragma unroll
    for (int mt = 0; mt < 2; mt++)
        #pragma unroll
        for (int nt = 0; nt < 8; nt++) {
            const int r0 = bm0 + wm + mt * 16 + g;
            const int c0 = bn0 + wn + nt * 8 + 2 * q;
            *reinterpret_cast<uint32_t*>(C + (size_t)r0 * N + c0) =
                packh2(acc[mt][nt][0], acc[mt][nt][1]);
            *reinterpret_cast<uint32_t*>(C + (size_t)(r0 + 8) * N + c0) =
                packh2(acc[mt][nt][2], acc[mt][nt][3]);
        }
}

// ---------------- small fp16 GEMM: 128x128x32, 4-stage, single sync ----------------
#define ASTG_H (128 * SAH)
#define STAGE_H (2 * ASTG_H)
#define GEMM_SMEM (4 * STAGE_H * 2)   // 81920 B

template <bool OTF>
__global__ __launch_bounds__(256, 2) void gemm_f16(
    const __half* __restrict__ A, const __half* __restrict__ Bt,
    void* __restrict__ Cv, int N, int K, float alpha) {
    extern __shared__ __half smh[];
    const uint32_t s_b = smem_u32(smh);

    const int tid = threadIdx.x;
    const int warp = tid >> 5, lane = tid & 31;
    const int g = lane >> 2, q = lane & 3;
    const int wm = (warp >> 1) * 32;
    const int wn = (warp & 1) * 64;
    const int bm0 = blockIdx.y * 128;
    const int bn0 = blockIdx.x * 128;
    const __half* Ab = A + (size_t)bm0 * K;
    const __half* Bb = Bt + (size_t)bn0 * K;

    const int lmA = (lane & 15) * SAH + ((lane >> 4) << 3);
    const int lmB = (((lane >> 4) << 3) + (lane & 7)) * SAH + (((lane >> 3) & 1) << 3);

    auto issue = [&](int stage, int kt) {
        const uint32_t base = s_b + stage * STAGE_H * 2;
        #pragma unroll
        for (int c = 0; c < 2; c++) {
            const int cid = tid + c * 256;
            const int row = cid >> 2, c8 = (cid & 3) * 8;
            cpa(base + (uint32_t)(row * SAH + c8) * 2,
                Ab + (size_t)row * K + kt + c8);
            cpa(base + ASTG_H * 2 + (uint32_t)(row * SAH + c8) * 2,
                Bb + (size_t)row * K + kt + c8);
        }
    };

    float acc[2][8][4];
    #pragma unroll
    for (int mt = 0; mt < 2; mt++)
        #pragma unroll
        for (int nt = 0; nt < 8; nt++)
            #pragma unroll
            for (int i = 0; i < 4; i++) acc[mt][nt][i] = 0.f;

    const int nk = K / 32;
    issue(0, 0);  CP_COMMIT;
    issue(1, 32); CP_COMMIT;
    issue(2, 64); CP_COMMIT;

    for (int t = 0; t < nk; t++) {
        CP_WAIT2;
        __syncthreads();
        const uint32_t cAb = s_b + ((t & 3) * STAGE_H) * 2;
        const uint32_t cBb = cAb + ASTG_H * 2;
        #pragma unroll
        for (int kk = 0; kk < 32; kk += 16) {
            uint32_t af[2][4];
            #pragma unroll
            for (int mt = 0; mt < 2; mt++)
                LDSM_X4(af[mt][0], af[mt][1], af[mt][2], af[mt][3],
                        cAb + (uint32_t)((wm + mt * 16) * SAH + kk + lmA) * 2);
            #pragma unroll
            for (int p = 0; p < 4; p++) {
                uint32_t b0, b1, b2, b3;
                LDSM_X4(b0, b1, b2, b3,
                        cBb + (uint32_t)((wn + p * 16) * SAH + kk + lmB) * 2);
                mma16(acc[0][2 * p],     af[0], b0, b1);
                mma16(acc[1][2 * p],     af[1], b0, b1);
                mma16(acc[0][2 * p + 1], af[0], b2, b3);
                mma16(acc[1][2 * p + 1], af[1], b2, b3);
            }
        }
        if (t + 3 < nk) issue((t + 3) & 3, (t + 3) * 32);
        CP_COMMIT;
    }

    #pragma unroll
    for (int mt = 0; mt < 2; mt++)
        #pragma unroll
        for (int nt = 0; nt < 8; nt++) {
            const int r0 = bm0 + wm + mt * 16 + g;
            const int c0 = bn0 + wn + nt * 8 + 2 * q;
            if (OTF) {
                __half* C = (__half*)Cv;
                *reinterpret_cast<uint32_t*>(C + (size_t)r0 * N + c0) =
                    packh2(acc[mt][nt][0] * alpha, acc[mt][nt][1] * alpha);
                *reinterpret_cast<uint32_t*>(C + (size_t)(r0 + 8) * N + c0) =
                    packh2(acc[mt][nt][2] * alpha, acc[mt][nt][3] * alpha);
            } else {
                float* C = (float*)Cv;
                *reinterpret_cast<float2*>(C + (size_t)r0 * N + c0) =
                    make_float2(acc[mt][nt][0] * alpha, acc[mt][nt][1] * alpha);
                *reinterpret_cast<float2*>(C + (size_t)(r0 + 8) * N + c0) =
                    make_float2(acc[mt][nt][2] * alpha, acc[mt][nt][3] * alpha);
            }
        }
}

// ---------------- flash attention: KV-split 2, 4-buffer ring, single sync ------
#define JC   64
#define KST  88
#define TILE_H (JC * KST)
#define KOFF(buf) ((buf) * TILE_H)
#define VOFF(buf) ((4 + (buf)) * TILE_H)
#define ATT_SMEM (8 * TILE_H * 2)           // 90112 B

__global__ __launch_bounds__(256, 1) void attention_kernel(
    const __half* __restrict__ Q, const __half* __restrict__ KV,
    float* __restrict__ Op, float* __restrict__ Lp) {
    extern __shared__ __half smh[];
    const uint32_t s_b = smem_u32(smh);

    const int bh = blockIdx.x;
    const int b = bh >> 3, h = bh & 7;
    const int split = blockIdx.y;
    const int tid = threadIdx.x, warp = tid >> 5, lane = tid & 31;
    const int g = lane >> 2, q = lane & 3;

    const __half* Kg = KV + ((size_t)(b * TM_) + split * KVSPLIT) * 1024 + h * DH_;
    const __half* Vg = Kg + INNER_;

    auto issue = [&](int buf, int j0) {
        #pragma unroll
        for (int p = 0; p < 2; p++) {
            const int cid = tid + p * 256;
            const int jj = cid >> 3, c8 = (cid & 7) * 8;
            cpa(s_b + (uint32_t)(KOFF(buf) + jj * KST + c8) * 2,
                Kg + (size_t)(j0 + jj) * 1024 + c8);
            cpa(s_b + (uint32_t)(VOFF(buf) + jj * KST + c8) * 2,
                Vg + (size_t)(j0 + jj) * 1024 + c8);
        }
    };

    const int qrow0 = b * NQ_ + warp * 32;
    uint32_t qa[2][4][4];
    #pragma unroll
    for (int mt = 0; mt < 2; mt++) {
        const __half* Qb = Q + (size_t)(qrow0 + mt * 16) * INNER_ + h * DH_;
        #pragma unroll
        for (int ks = 0; ks < 4; ks++) {
            const __half* p = Qb + (size_t)g * INNER_ + ks * 16 + 2 * q;
            qa[mt][ks][0] = *reinterpret_cast<const uint32_t*>(p);
            qa[mt][ks][1] = *reinterpret_cast<const uint32_t*>(p + 8 * INNER_);
            qa[mt][ks][2] = *reinterpret_cast<const uint32_t*>(p + 8);
            qa[mt][ks][3] = *reinterpret_cast<const uint32_t*>(p + 8 * INNER_ + 8);
        }
    }

    float oacc[2][8][4];
    #pragma unroll
    for (int mt = 0; mt < 2; mt++)
        #pragma unroll
        for (int nt = 0; nt < 8; nt++)
            #pragma unroll
            for (int i = 0; i < 4; i++) oacc[mt][nt][i] = 0.f;
    float lr[2][2] = {{0.f, 0.f}, {0.f, 0.f}};

    const int lmB = (((lane >> 4) << 3) + (lane & 7)) * KST + (((lane >> 3) & 1) << 3);
    const int lm_row = lane & 15;
    const int lm_col = (lane >> 4) * 8;

    const int NC = KVSPLIT / JC;
    issue(0, 0); CP_COMMIT;

    for (int jc = 0; jc < NC; jc++) {
        const int buf = jc & 3;
        if (jc + 1 < NC) issue((jc + 1) & 3, (jc + 1) * JC);
        CP_COMMIT;
        CP_WAIT1;
        __syncthreads();

        float sacc[2][8][4];
        #pragma unroll
        for (int mt = 0; mt < 2; mt++)
            #pragma unroll
            for (int nt = 0; nt < 8; nt++)
                #pragma unroll
                for (int i = 0; i < 4; i++) sacc[mt][nt][i] = 0.f;
        const uint32_t kb = s_b + (uint32_t)KOFF(buf) * 2;
        #pragma unroll
        for (int ks = 0; ks < 4; ks++) {
            #pragma unroll
            for (int p = 0; p < 4; p++) {
                uint32_t b0, b1, b2, b3;
                LDSM_X4(b0, b1, b2, b3,
                        kb + (uint32_t)(p * 16 * KST + ks * 16 + lmB) * 2);
                #pragma unroll
                for (int mt = 0; mt < 2; mt++) {
                    mma16(sacc[mt][2 * p],     qa[mt][ks], b0, b1);
                    mma16(sacc[mt][2 * p + 1], qa[mt][ks], b2, b3);
                }
            }
        }

        uint32_t pa[2][4][4];
        #pragma unroll
        for (int mt = 0; mt < 2; mt++) {
            float ls0 = 0.f, ls1 = 0.f;
            #pragma unroll
            for (int ks = 0; ks < 4; ks++) {
                pa[mt][ks][0] = h2e2(packh2(sacc[mt][2 * ks][0],     sacc[mt][2 * ks][1]));
                pa[mt][ks][1] = h2e2(packh2(sacc[mt][2 * ks][2],     sacc[mt][2 * ks][3]));
                pa[mt][ks][2] = h2e2(packh2(sacc[mt][2 * ks + 1][0], sacc[mt][2 * ks + 1][1]));
                pa[mt][ks][3] = h2e2(packh2(sacc[mt][2 * ks + 1][2], sacc[mt][2 * ks + 1][3]));
                float2 a0 = h22f2(pa[mt][ks][0]), a2 = h22f2(pa[mt][ks][2]);
                ls0 += (a0.x + a0.y) + (a2.x + a2.y);
                float2 a1 = h22f2(pa[mt][ks][1]), a3 = h22f2(pa[mt][ks][3]);
                ls1 += (a1.x + a1.y) + (a3.x + a3.y);
            }
            lr[mt][0] += ls0;
            lr[mt][1] += ls1;
        }

        const uint32_t vbase =
            s_b + (uint32_t)(VOFF(buf) + lm_row * KST + lm_col) * 2;
        #pragma unroll
        for (int ks = 0; ks < 4; ks++) {
            #pragma unroll
            for (int dg = 0; dg < 4; dg++) {
                uint32_t v0, v1, v2, v3;
                LDSM_T(v0, v1, v2, v3,
                       vbase + (uint32_t)(ks * 16 * KST + dg * 16) * 2);
                #pragma unroll
                for (int mt = 0; mt < 2; mt++) {
                    mma16(oacc[mt][dg * 2],     pa[mt][ks], v0, v1);
                    mma16(oacc[mt][dg * 2 + 1], pa[mt][ks], v2, v3);
                }
            }
        }
        // no trailing sync: 4-buffer ring bounds skew to 1 iteration
    }

    float* Ob = Op + (size_t)split * BNQ * INNER_;
    #pragma unroll
    for (int mt = 0; mt < 2; mt++) {
        const int r0 = qrow0 + mt * 16 + g;
        #pragma unroll
        for (int nt = 0; nt < 8; nt++) {
            const int c0 = h * DH_ + nt * 8 + 2 * q;
            *reinterpret_cast<float2*>(Ob + (size_t)r0 * INNER_ + c0) =
                make_float2(oacc[mt][nt][0], oacc[mt][nt][1]);
            *reinterpret_cast<float2*>(Ob + (size_t)(r0 + 8) * INNER_ + c0) =
                make_float2(oacc[mt][nt][2], oacc[mt][nt][3]);
        }
        float l0 = lr[mt][0], l1 = lr[mt][1];
        #pragma unroll
        for (int o = 1; o < 4; o <<= 1) {
            l0 += __shfl_xor_sync(0xffffffffu, l0, o);
            l1 += __shfl_xor_sync(0xffffffffu, l1, o);
        }
        if (q == 0) {
            Lp[((size_t)split * BNQ + r0) * HH + h]     = l0;
            Lp[((size_t)split * BNQ + r0 + 8) * HH + h] = l1;
        }
    }
}

// ---------------- attention reduce ----------------
__global__ __launch_bounds__(256) void att_reduce(
    const float* __restrict__ Op, const float* __restrict__ Lp,
    __half* __restrict__ att) {
    const int r = blockIdx.x;
    const int c = threadIdx.x * 2;
    const int h = c >> 6;
    float ax = 0.f, ay = 0.f, l = 0.f;
    #pragma unroll
    for (int s = 0; s < NSPLIT; s++) {
        const float2 a = *reinterpret_cast<const float2*>(
            Op + ((size_t)s * BNQ + r) * INNER_ + c);
        ax += a.x; ay += a.y;
        l += Lp[((size_t)s * BNQ + r) * HH + h];
    }
    const float inv = 1.f / l;
    *reinterpret_cast<uint32_t*>(att + (size_t)r * INNER_ + c) =
        packh2(ax * inv, ay * inv);
}

// ---------------- launch ----------------
extern "C" void kernel_launch(void* const* d_in, const int* in_sizes, int n_in,
                              void* d_out, int out_size) {
    const float* x    = (const float*)d_in[0];
    const float* k_v  = (const float*)d_in[1];
    const float* g_q  = (const float*)d_in[2];
    const float* b_q  = (const float*)d_in[3];
    const float* g_kv = (const float*)d_in[4];
    const float* b_kv = (const float*)d_in[5];
    const float* Wq   = (const float*)d_in[6];
    const float* Wkv  = (const float*)d_in[7];
    const float* Wo   = (const float*)d_in[8];
    float* out = (float*)d_out;

    __half *xn, *kvn, *wqT, *wkvT, *woT, *qbuf, *kvp, *att;
    float *attp, *lsum;
    cudaGetSymbolAddress((void**)&xn,   g_xn);
    cudaGetSymbolAddress((void**)&kvn,  g_kvn);
    cudaGetSymbolAddress((void**)&wqT,  g_wqT);
    cudaGetSymbolAddress((void**)&wkvT, g_wkvT);
    cudaGetSymbolAddress((void**)&woT,  g_woT);
    cudaGetSymbolAddress((void**)&qbuf, g_qbuf);
    cudaGetSymbolAddress((void**)&kvp,  g_kvp);
    cudaGetSymbolAddress((void**)&att,  g_att);
    cudaGetSymbolAddress((void**)&attp, g_attp);
    cudaGetSymbolAddress((void**)&lsum, g_lsum);

    cudaFuncSetAttribute(gemm_f16<true>,
                         cudaFuncAttributeMaxDynamicSharedMemorySize, GEMM_SMEM);
    cudaFuncSetAttribute(gemm_f16<false>,
                         cudaFuncAttributeMaxDynamicSharedMemorySize, GEMM_SMEM);
    cudaFuncSetAttribute(gemm_f16_big,
                         cudaFuncAttributeMaxDynamicSharedMemorySize, BG_SMEM);
    cudaFuncSetAttribute(attention_kernel,
                         cudaFuncAttributeMaxDynamicSharedMemorySize, ATT_SMEM);

    // one-time stream/event creation (resource setup, not per-call work;
    // every call enqueues the identical launch DAG)
    static cudaStream_t s_side = [] {
        cudaStream_t s; cudaStreamCreateWithFlags(&s, cudaStreamNonBlocking); return s;
    }();
    static cudaEvent_t ev_fork = [] {
        cudaEvent_t e; cudaEventCreateWithFlags(&e, cudaEventDisableTiming); return e;
    }();
    static cudaEvent_t ev_join = [] {
        cudaEvent_t e; cudaEventCreateWithFlags(&e, cudaEventDisableTiming); return e;
    }();

    // fork side stream off the main (capture) stream
    cudaEventRecord(ev_fork, 0);
    cudaStreamWaitEvent(s_side, ev_fork, 0);

    // ---- side branch (independent of kv path): q branch + Wo transpose ----
    ln_conv<DIM_><<<BNQ, 256, 0, s_side>>>(x, g_q, b_q, xn);
    wconvT<<<dim3(INNER_ / 32, DIM_ / 32), dim3(32, 8), 0, s_side>>>(
        Wq, wqT, DIM_, INNER_);
    wconvT<<<dim3(DIM_ / 32, INNER_ / 32), dim3(32, 8), 0, s_side>>>(
        Wo, woT, INNER_, DIM_);
    gemm_f16<true><<<dim3(INNER_ / 128, BNQ / 128), 256, GEMM_SMEM, s_side>>>(
        xn, wqT, qbuf, INNER_, DIM_, QSCALE);
    cudaEventRecord(ev_join, s_side);

    // ---- main branch: kv path ----
    ln_conv<KVD_><<<BTM, 256>>>(k_v, g_kv, b_kv, kvn);
    wconvT<<<dim3(1024 / 32, KVD_ / 32), dim3(32, 8)>>>(Wkv, wkvT, KVD_, 1024);
    gemm_f16_big<<<dim3(1024 / 128, BTM / 256), 512, BG_SMEM>>>(
        kvn, wkvT, kvp, 1024, KVD_);

    // join: attention needs qbuf (side) + kvp (main); out proj needs woT (side)
    cudaStreamWaitEvent(0, ev_join, 0);

    attention_kernel<<<dim3(BB * HH, NSPLIT), 256, ATT_SMEM>>>(qbuf, kvp, attp, lsum);
    att_reduce<<<BNQ, 256>>>(attp, lsum, att);
    gemm_f16<false><<<dim3(DIM_ / 128, BNQ / 128), 256, GEMM_SMEM>>>(
        att, woT, out, DIM_, INNER_, 1.f);
}

// round 17
// speedup vs baseline: 1.0983x; 1.0398x over previous
#include <cuda_runtime.h>
#include <cuda_fp16.h>
#include <cstdint>

// ---------------- problem constants ----------------
#define BB     8
#define NQ_    256
#define DIM_   768
#define KVD_   1024
#define HH     8
#define DH_    64
#define INNER_ 512
#define TM_    8192
#define BNQ    2048
#define BTM    65536
#define LN_EPS 1e-5f

// q scale folded with log2(e): 0.125 * 1.4426950408889634
#define QSCALE 0.18033688011112043f

#define NSPLIT 2
#define KVSPLIT (TM_ / NSPLIT)              // 4096

// ---------------- scratch (device globals) ----------------
__device__ __half g_xn[BNQ * DIM_];
__device__ __half g_kvn[(size_t)BTM * KVD_];
__device__ __half g_wqT[INNER_ * DIM_];
__device__ __half g_wkvT[1024 * KVD_];
__device__ __half g_woT[DIM_ * INNER_];
__device__ __half g_qbuf[BNQ * INNER_];
__device__ __half g_kvp[(size_t)BTM * 1024];
__device__ __half g_att[BNQ * INNER_];
__device__ float  g_attp[NSPLIT * BNQ * INNER_];
__device__ float  g_lsum[NSPLIT * BNQ * HH];

// ---------------- helpers ----------------
__device__ __forceinline__ uint32_t packh2(float lo, float hi) {
    uint32_t r;
    asm("cvt.rn.f16x2.f32 %0, %1, %2;" : "=r"(r) : "f"(hi), "f"(lo));
    return r;
}

__device__ __forceinline__ uint32_t h2e2(uint32_t x) {
    __half2 h = *reinterpret_cast<__half2*>(&x);
    h = h2exp2(h);
    return *reinterpret_cast<uint32_t*>(&h);
}

__device__ __forceinline__ float2 h22f2(uint32_t x) {
    __half2 h = *reinterpret_cast<__half2*>(&x);
    return __half22float2(h);
}

__device__ __forceinline__ void mma16(float c[4], const uint32_t a[4],
                                      uint32_t b0, uint32_t b1) {
    asm volatile("mma.sync.aligned.m16n8k16.row.col.f32.f16.f16.f32 "
        "{%0,%1,%2,%3}, {%4,%5,%6,%7}, {%8,%9}, {%0,%1,%2,%3};"
        : "+f"(c[0]), "+f"(c[1]), "+f"(c[2]), "+f"(c[3])
        : "r"(a[0]), "r"(a[1]), "r"(a[2]), "r"(a[3]), "r"(b0), "r"(b1));
}

__device__ __forceinline__ void cpa(uint32_t dst, const void* src) {
    asm volatile("cp.async.cg.shared.global [%0], [%1], 16;" :: "r"(dst), "l"(src));
}
#define CP_COMMIT asm volatile("cp.async.commit_group;")
#define CP_WAIT1  asm volatile("cp.async.wait_group 1;")
#define CP_WAIT2  asm volatile("cp.async.wait_group 2;")

__device__ __forceinline__ uint32_t smem_u32(const void* p) {
    return (uint32_t)__cvta_generic_to_shared(p);
}

#define LDSM_X4(r0, r1, r2, r3, addr) \
    asm volatile("ldmatrix.sync.aligned.m8n8.x4.shared.b16 {%0,%1,%2,%3}, [%4];" \
                 : "=r"(r0), "=r"(r1), "=r"(r2), "=r"(r3) : "r"(addr))
#define LDSM_T(r0, r1, r2, r3, addr) \
    asm volatile("ldmatrix.sync.aligned.m8n8.x4.trans.shared.b16 {%0,%1,%2,%3}, [%4];" \
                 : "=r"(r0), "=r"(r1), "=r"(r2), "=r"(r3) : "r"(addr))

// ---------------- LayerNorm + fp16 convert, warp-per-row ----------------
// 8 warps/block, 1 row/warp, RL/128 float4s per lane in registers (MLP 6-8),
// warp-shuffle reduction only; no smem, no block barrier.
template <int RL>
__global__ __launch_bounds__(256) void ln_conv(const float* __restrict__ X,
                                               const float* __restrict__ gam,
                                               const float* __restrict__ bet,
                                               __half* __restrict__ Y) {
    constexpr int NV = RL / 128;            // float4s per lane
    const int warp = threadIdx.x >> 5, lane = threadIdx.x & 31;
    const int row = blockIdx.x * 8 + warp;
    const float4* xr = reinterpret_cast<const float4*>(X + (size_t)row * RL);

    float4 v[NV];
    float s = 0.f, ss = 0.f;
    #pragma unroll
    for (int i = 0; i < NV; i++) {
        v[i] = xr[lane + i * 32];
        s  += (v[i].x + v[i].y) + (v[i].z + v[i].w);
        ss += v[i].x * v[i].x + v[i].y * v[i].y + v[i].z * v[i].z + v[i].w * v[i].w;
    }
    #pragma unroll
    for (int o = 16; o; o >>= 1) {
        s  += __shfl_xor_sync(0xffffffffu, s, o);
        ss += __shfl_xor_sync(0xffffffffu, ss, o);
    }
    const float m = s / (float)RL;
    const float r = rsqrtf(ss / (float)RL - m * m + LN_EPS);

    uint2* yr = reinterpret_cast<uint2*>(Y + (size_t)row * RL);
    #pragma unroll
    for (int i = 0; i < NV; i++) {
        const int c = lane + i * 32;
        const float4 gv = reinterpret_cast<const float4*>(gam)[c];
        const float4 bv = reinterpret_cast<const float4*>(bet)[c];
        uint2 o;
        o.x = packh2((v[i].x - m) * r * gv.x + bv.x, (v[i].y - m) * r * gv.y + bv.y);
        o.y = packh2((v[i].z - m) * r * gv.z + bv.z, (v[i].w - m) * r * gv.w + bv.w);
        yr[c] = o;
    }
}

// ---------------- weight transpose ----------------
__global__ __launch_bounds__(256) void wconvT(const float* __restrict__ W,
                                              __half* __restrict__ Wt,
                                              int K, int N) {
    __shared__ __half t[32][33];
    const int tx = threadIdx.x, ty = threadIdx.y;
    const int k0 = blockIdx.y * 32, n0 = blockIdx.x * 32;
    #pragma unroll
    for (int i = 0; i < 4; i++)
        t[ty + i * 8][tx] = __float2half_rn(W[(size_t)(k0 + ty + i * 8) * N + n0 + tx]);
    __syncthreads();
    #pragma unroll
    for (int i = 0; i < 4; i++)
        Wt[(size_t)(n0 + ty + i * 8) * K + k0 + tx] = t[tx][ty + i * 8];
}

// ====== BIG GEMM (exact R11): 256x128 CTA, 512 thr (16 warps, 32x64 each), ======
// ====== BK=32, 4-stage, single sync, prefetch after compute ====================
#define SAH 40
#define BG_A_H (256 * SAH)
#define BG_B_H (128 * SAH)
#define BG_STG_H (BG_A_H + BG_B_H)
#define BG_SMEM (4 * BG_STG_H * 2)          // 122880 B

__global__ __launch_bounds__(512, 1) void gemm_f16_big(
    const __half* __restrict__ A, const __half* __restrict__ Bt,
    __half* __restrict__ C, int N, int K) {
    extern __shared__ __half smh[];
    const uint32_t s_b = smem_u32(smh);

    const int tid = threadIdx.x;
    const int warp = tid >> 5, lane = tid & 31;
    const int g = lane >> 2, q = lane & 3;
    const int wm = (warp >> 1) * 32;
    const int wn = (warp & 1) * 64;
    const int bm0 = blockIdx.y * 256;
    const int bn0 = blockIdx.x * 128;
    const __half* Ab = A + (size_t)bm0 * K;
    const __half* Bb = Bt + (size_t)bn0 * K;

    const int lmA = (lane & 15) * SAH + ((lane >> 4) << 3);
    const int lmB = (((lane >> 4) << 3) + (lane & 7)) * SAH + (((lane >> 3) & 1) << 3);

    auto issue = [&](int stage, int kt) {
        const uint32_t base = s_b + stage * BG_STG_H * 2;
        #pragma unroll
        for (int c = 0; c < 2; c++) {
            const int cid = tid + c * 512;
            const int row = cid >> 2, c8 = (cid & 3) * 8;
            cpa(base + (uint32_t)(row * SAH + c8) * 2,
                Ab + (size_t)row * K + kt + c8);
        }
        {
            const int row = tid >> 2, c8 = (tid & 3) * 8;
            cpa(base + BG_A_H * 2 + (uint32_t)(row * SAH + c8) * 2,
                Bb + (size_t)row * K + kt + c8);
        }
    };

    float acc[2][8][4];
    #pragma unroll
    for (int mt = 0; mt < 2; mt++)
        #pragma unroll
        for (int nt = 0; nt < 8; nt++)
            #pragma unroll
            for (int i = 0; i < 4; i++) acc[mt][nt][i] = 0.f;

    const int nk = K / 32;
    issue(0, 0);  CP_COMMIT;
    issue(1, 32); CP_COMMIT;
    issue(2, 64); CP_COMMIT;

    for (int t = 0; t < nk; t++) {
        CP_WAIT2;
        __syncthreads();
        const uint32_t cAb = s_b + ((t & 3) * BG_STG_H) * 2;
        const uint32_t cBb = cAb + BG_A_H * 2;
        #pragma unroll
        for (int kk = 0; kk < 32; kk += 16) {
            uint32_t af[2][4];
            #pragma unroll
            for (int mt = 0; mt < 2; mt++)
                LDSM_X4(af[mt][0], af[mt][1], af[mt][2], af[mt][3],
                        cAb + (uint32_t)((wm + mt * 16) * SAH + kk + lmA) * 2);
            #pragma unroll
            for (int p = 0; p < 4; p++) {
                uint32_t b0, b1, b2, b3;
                LDSM_X4(b0, b1, b2, b3,
                        cBb + (uint32_t)((wn + p * 16) * SAH + kk + lmB) * 2);
                mma16(acc[0][2 * p],     af[0], b0, b1);
                mma16(acc[1][2 * p],     af[1], b0, b1);
                mma16(acc[0][2 * p + 1], af[0], b2, b3);
                mma16(acc[1][2 * p + 1], af[1], b2, b3);
            }
        }
        if (t + 3 < nk) issue((t + 3) & 3, (t + 3) * 32);
        CP_COMMIT;
    }

    #pragma unroll
    for (int mt = 0; mt < 2; mt++)
        #pragma unroll
        for (int nt = 0; nt < 8; nt++) {
            const int r0 = bm0 + wm + mt * 16 + g;
            const int c0 = bn0 + wn + nt * 8 + 2 * q;
            *reinterpret_cast<uint32_t*>(C + (size_t)r0 * N + c0) =
                packh2(acc[mt][nt][0], acc[mt][nt][1]);
            *reinterpret_cast<uint32_t*>(C + (size_t)(r0 + 8) * N + c0) =
                packh2(acc[mt][nt][2], acc[mt][nt][3]);
        }
}

// ---------------- small fp16 GEMM: 128x128x32, 4-stage, single sync ----------------
#define ASTG_H (128 * SAH)
#define STAGE_H (2 * ASTG_H)
#define GEMM_SMEM (4 * STAGE_H * 2)   // 81920 B

template <bool OTF>
__global__ __launch_bounds__(256, 2) void gemm_f16(
    const __half* __restrict__ A, const __half* __restrict__ Bt,
    void* __restrict__ Cv, int N, int K, float alpha) {
    extern __shared__ __half smh[];
    const uint32_t s_b = smem_u32(smh);

    const int tid = threadIdx.x;
    const int warp = tid >> 5, lane = tid & 31;
    const int g = lane >> 2, q = lane & 3;
    const int wm = (warp >> 1) * 32;
    const int wn = (warp & 1) * 64;
    const int bm0 = blockIdx.y * 128;
    const int bn0 = blockIdx.x * 128;
    const __half* Ab = A + (size_t)bm0 * K;
    const __half* Bb = Bt + (size_t)bn0 * K;

    const int lmA = (lane & 15) * SAH + ((lane >> 4) << 3);
    const int lmB = (((lane >> 4) << 3) + (lane & 7)) * SAH + (((lane >> 3) & 1) << 3);

    auto issue = [&](int stage, int kt) {
        const uint32_t base = s_b + stage * STAGE_H * 2;
        #pragma unroll
        for (int c = 0; c < 2; c++) {
            const int cid = tid + c * 256;
            const int row = cid >> 2, c8 = (cid & 3) * 8;
            cpa(base + (uint32_t)(row * SAH + c8) * 2,
                Ab + (size_t)row * K + kt + c8);
            cpa(base + ASTG_H * 2 + (uint32_t)(row * SAH + c8) * 2,
                Bb + (size_t)row * K + kt + c8);
        }
    };

    float acc[2][8][4];
    #pragma unroll
    for (int mt = 0; mt < 2; mt++)
        #pragma unroll
        for (int nt = 0; nt < 8; nt++)
            #pragma unroll
            for (int i = 0; i < 4; i++) acc[mt][nt][i] = 0.f;

    const int nk = K / 32;
    issue(0, 0);  CP_COMMIT;
    issue(1, 32); CP_COMMIT;
    issue(2, 64); CP_COMMIT;

    for (int t = 0; t < nk; t++) {
        CP_WAIT2;
        __syncthreads();
        const uint32_t cAb = s_b + ((t & 3) * STAGE_H) * 2;
        const uint32_t cBb = cAb + ASTG_H * 2;
        #pragma unroll
        for (int kk = 0; kk < 32; kk += 16) {
            uint32_t af[2][4];
            #pragma unroll
            for (int mt = 0; mt < 2; mt++)
                LDSM_X4(af[mt][0], af[mt][1], af[mt][2], af[mt][3],
                        cAb + (uint32_t)((wm + mt * 16) * SAH + kk + lmA) * 2);
            #pragma unroll
            for (int p = 0; p < 4; p++) {
                uint32_t b0, b1, b2, b3;
                LDSM_X4(b0, b1, b2, b3,
                        cBb + (uint32_t)((wn + p * 16) * SAH + kk + lmB) * 2);
                mma16(acc[0][2 * p],     af[0], b0, b1);
                mma16(acc[1][2 * p],     af[1], b0, b1);
                mma16(acc[0][2 * p + 1], af[0], b2, b3);
                mma16(acc[1][2 * p + 1], af[1], b2, b3);
            }
        }
        if (t + 3 < nk) issue((t + 3) & 3, (t + 3) * 32);
        CP_COMMIT;
    }

    #pragma unroll
    for (int mt = 0; mt < 2; mt++)
        #pragma unroll
        for (int nt = 0; nt < 8; nt++) {
            const int r0 = bm0 + wm + mt * 16 + g;
            const int c0 = bn0 + wn + nt * 8 + 2 * q;
            if (OTF) {
                __half* C = (__half*)Cv;
                *reinterpret_cast<uint32_t*>(C + (size_t)r0 * N + c0) =
                    packh2(acc[mt][nt][0] * alpha, acc[mt][nt][1] * alpha);
                *reinterpret_cast<uint32_t*>(C + (size_t)(r0 + 8) * N + c0) =
                    packh2(acc[mt][nt][2] * alpha, acc[mt][nt][3] * alpha);
            } else {
                float* C = (float*)Cv;
                *reinterpret_cast<float2*>(C + (size_t)r0 * N + c0) =
                    make_float2(acc[mt][nt][0] * alpha, acc[mt][nt][1] * alpha);
                *reinterpret_cast<float2*>(C + (size_t)(r0 + 8) * N + c0) =
                    make_float2(acc[mt][nt][2] * alpha, acc[mt][nt][3] * alpha);
            }
        }
}

// ---------------- flash attention: KV-split 2, 4-buffer ring, single sync ------
#define JC   64
#define KST  88
#define TILE_H (JC * KST)
#define KOFF(buf) ((buf) * TILE_H)
#define VOFF(buf) ((4 + (buf)) * TILE_H)
#define ATT_SMEM (8 * TILE_H * 2)           // 90112 B

__global__ __launch_bounds__(256, 1) void attention_kernel(
    const __half* __restrict__ Q, const __half* __restrict__ KV,
    float* __restrict__ Op, float* __restrict__ Lp) {
    extern __shared__ __half smh[];
    const uint32_t s_b = smem_u32(smh);

    const int bh = blockIdx.x;
    const int b = bh >> 3, h = bh & 7;
    const int split = blockIdx.y;
    const int tid = threadIdx.x, warp = tid >> 5, lane = tid & 31;
    const int g = lane >> 2, q = lane & 3;

    const __half* Kg = KV + ((size_t)(b * TM_) + split * KVSPLIT) * 1024 + h * DH_;
    const __half* Vg = Kg + INNER_;

    auto issue = [&](int buf, int j0) {
        #pragma unroll
        for (int p = 0; p < 2; p++) {
            const int cid = tid + p * 256;
            const int jj = cid >> 3, c8 = (cid & 7) * 8;
            cpa(s_b + (uint32_t)(KOFF(buf) + jj * KST + c8) * 2,
                Kg + (size_t)(j0 + jj) * 1024 + c8);
            cpa(s_b + (uint32_t)(VOFF(buf) + jj * KST + c8) * 2,
                Vg + (size_t)(j0 + jj) * 1024 + c8);
        }
    };

    const int qrow0 = b * NQ_ + warp * 32;
    uint32_t qa[2][4][4];
    #pragma unroll
    for (int mt = 0; mt < 2; mt++) {
        const __half* Qb = Q + (size_t)(qrow0 + mt * 16) * INNER_ + h * DH_;
        #pragma unroll
        for (int ks = 0; ks < 4; ks++) {
            const __half* p = Qb + (size_t)g * INNER_ + ks * 16 + 2 * q;
            qa[mt][ks][0] = *reinterpret_cast<const uint32_t*>(p);
            qa[mt][ks][1] = *reinterpret_cast<const uint32_t*>(p + 8 * INNER_);
            qa[mt][ks][2] = *reinterpret_cast<const uint32_t*>(p + 8);
            qa[mt][ks][3] = *reinterpret_cast<const uint32_t*>(p + 8 * INNER_ + 8);
        }
    }

    float oacc[2][8][4];
    #pragma unroll
    for (int mt = 0; mt < 2; mt++)
        #pragma unroll
        for (int nt = 0; nt < 8; nt++)
            #pragma unroll
            for (int i = 0; i < 4; i++) oacc[mt][nt][i] = 0.f;
    float lr[2][2] = {{0.f, 0.f}, {0.f, 0.f}};

    const int lmB = (((lane >> 4) << 3) + (lane & 7)) * KST + (((lane >> 3) & 1) << 3);
    const int lm_row = lane & 15;
    const int lm_col = (lane >> 4) * 8;

    const int NC = KVSPLIT / JC;
    issue(0, 0); CP_COMMIT;

    for (int jc = 0; jc < NC; jc++) {
        const int buf = jc & 3;
        if (jc + 1 < NC) issue((jc + 1) & 3, (jc + 1) * JC);
        CP_COMMIT;
        CP_WAIT1;
        __syncthreads();

        float sacc[2][8][4];
        #pragma unroll
        for (int mt = 0; mt < 2; mt++)
            #pragma unroll
            for (int nt = 0; nt < 8; nt++)
                #pragma unroll
                for (int i = 0; i < 4; i++) sacc[mt][nt][i] = 0.f;
        const uint32_t kb = s_b + (uint32_t)KOFF(buf) * 2;
        #pragma unroll
        for (int ks = 0; ks < 4; ks++) {
            #pragma unroll
            for (int p = 0; p < 4; p++) {
                uint32_t b0, b1, b2, b3;
                LDSM_X4(b0, b1, b2, b3,
                        kb + (uint32_t)(p * 16 * KST + ks * 16 + lmB) * 2);
                #pragma unroll
                for (int mt = 0; mt < 2; mt++) {
                    mma16(sacc[mt][2 * p],     qa[mt][ks], b0, b1);
                    mma16(sacc[mt][2 * p + 1], qa[mt][ks], b2, b3);
                }
            }
        }

        uint32_t pa[2][4][4];
        #pragma unroll
        for (int mt = 0; mt < 2; mt++) {
            float ls0 = 0.f, ls1 = 0.f;
            #pragma unroll
            for (int ks = 0; ks < 4; ks++) {
                pa[mt][ks][0] = h2e2(packh2(sacc[mt][2 * ks][0],     sacc[mt][2 * ks][1]));
                pa[mt][ks][1] = h2e2(packh2(sacc[mt][2 * ks][2],     sacc[mt][2 * ks][3]));
                pa[mt][ks][2] = h2e2(packh2(sacc[mt][2 * ks + 1][0], sacc[mt][2 * ks + 1][1]));
                pa[mt][ks][3] = h2e2(packh2(sacc[mt][2 * ks + 1][2], sacc[mt][2 * ks + 1][3]));
                float2 a0 = h22f2(pa[mt][ks][0]), a2 = h22f2(pa[mt][ks][2]);
                ls0 += (a0.x + a0.y) + (a2.x + a2.y);
                float2 a1 = h22f2(pa[mt][ks][1]), a3 = h22f2(pa[mt][ks][3]);
                ls1 += (a1.x + a1.y) + (a3.x + a3.y);
            }
            lr[mt][0] += ls0;
            lr[mt][1] += ls1;
        }

        const uint32_t vbase =
            s_b + (uint32_t)(VOFF(buf) + lm_row * KST + lm_col) * 2;
        #pragma unroll
        for (int ks = 0; ks < 4; ks++) {
            #pragma unroll
            for (int dg = 0; dg < 4; dg++) {
                uint32_t v0, v1, v2, v3;
                LDSM_T(v0, v1, v2, v3,
                       vbase + (uint32_t)(ks * 16 * KST + dg * 16) * 2);
                #pragma unroll
                for (int mt = 0; mt < 2; mt++) {
                    mma16(oacc[mt][dg * 2],     pa[mt][ks], v0, v1);
                    mma16(oacc[mt][dg * 2 + 1], pa[mt][ks], v2, v3);
                }
            }
        }
        // no trailing sync: 4-buffer ring bounds skew to 1 iteration
    }

    float* Ob = Op + (size_t)split * BNQ * INNER_;
    #pragma unroll
    for (int mt = 0; mt < 2; mt++) {
        const int r0 = qrow0 + mt * 16 + g;
        #pragma unroll
        for (int nt = 0; nt < 8; nt++) {
            const int c0 = h * DH_ + nt * 8 + 2 * q;
            *reinterpret_cast<float2*>(Ob + (size_t)r0 * INNER_ + c0) =
                make_float2(oacc[mt][nt][0], oacc[mt][nt][1]);
            *reinterpret_cast<float2*>(Ob + (size_t)(r0 + 8) * INNER_ + c0) =
                make_float2(oacc[mt][nt][2], oacc[mt][nt][3]);
        }
        float l0 = lr[mt][0], l1 = lr[mt][1];
        #pragma unroll
        for (int o = 1; o < 4; o <<= 1) {
            l0 += __shfl_xor_sync(0xffffffffu, l0, o);
            l1 += __shfl_xor_sync(0xffffffffu, l1, o);
        }
        if (q == 0) {
            Lp[((size_t)split * BNQ + r0) * HH + h]     = l0;
            Lp[((size_t)split * BNQ + r0 + 8) * HH + h] = l1;
        }
    }
}

// ---------------- attention reduce ----------------
__global__ __launch_bounds__(256) void att_reduce(
    const float* __restrict__ Op, const float* __restrict__ Lp,
    __half* __restrict__ att) {
    const int r = blockIdx.x;
    const int c = threadIdx.x * 2;
    const int h = c >> 6;
    float ax = 0.f, ay = 0.f, l = 0.f;
    #pragma unroll
    for (int s = 0; s < NSPLIT; s++) {
        const float2 a = *reinterpret_cast<const float2*>(
            Op + ((size_t)s * BNQ + r) * INNER_ + c);
        ax += a.x; ay += a.y;
        l += Lp[((size_t)s * BNQ + r) * HH + h];
    }
    const float inv = 1.f / l;
    *reinterpret_cast<uint32_t*>(att + (size_t)r * INNER_ + c) =
        packh2(ax * inv, ay * inv);
}

// ---------------- launch ----------------
extern "C" void kernel_launch(void* const* d_in, const int* in_sizes, int n_in,
                              void* d_out, int out_size) {
    const float* x    = (const float*)d_in[0];
    const float* k_v  = (const float*)d_in[1];
    const float* g_q  = (const float*)d_in[2];
    const float* b_q  = (const float*)d_in[3];
    const float* g_kv = (const float*)d_in[4];
    const float* b_kv = (const float*)d_in[5];
    const float* Wq   = (const float*)d_in[6];
    const float* Wkv  = (const float*)d_in[7];
    const float* Wo   = (const float*)d_in[8];
    float* out = (float*)d_out;

    __half *xn, *kvn, *wqT, *wkvT, *woT, *qbuf, *kvp, *att;
    float *attp, *lsum;
    cudaGetSymbolAddress((void**)&xn,   g_xn);
    cudaGetSymbolAddress((void**)&kvn,  g_kvn);
    cudaGetSymbolAddress((void**)&wqT,  g_wqT);
    cudaGetSymbolAddress((void**)&wkvT, g_wkvT);
    cudaGetSymbolAddress((void**)&woT,  g_woT);
    cudaGetSymbolAddress((void**)&qbuf, g_qbuf);
    cudaGetSymbolAddress((void**)&kvp,  g_kvp);
    cudaGetSymbolAddress((void**)&att,  g_att);
    cudaGetSymbolAddress((void**)&attp, g_attp);
    cudaGetSymbolAddress((void**)&lsum, g_lsum);

    cudaFuncSetAttribute(gemm_f16<true>,
                         cudaFuncAttributeMaxDynamicSharedMemorySize, GEMM_SMEM);
    cudaFuncSetAttribute(gemm_f16<false>,
                         cudaFuncAttributeMaxDynamicSharedMemorySize, GEMM_SMEM);
    cudaFuncSetAttribute(gemm_f16_big,
                         cudaFuncAttributeMaxDynamicSharedMemorySize, BG_SMEM);
    cudaFuncSetAttribute(attention_kernel,
                         cudaFuncAttributeMaxDynamicSharedMemorySize, ATT_SMEM);

    // one-time stream/event creation
    static cudaStream_t s_side = [] {
        cudaStream_t s; cudaStreamCreateWithFlags(&s, cudaStreamNonBlocking); return s;
    }();
    static cudaEvent_t ev_fork = [] {
        cudaEvent_t e; cudaEventCreateWithFlags(&e, cudaEventDisableTiming); return e;
    }();
    static cudaEvent_t ev_wkv = [] {
        cudaEvent_t e; cudaEventCreateWithFlags(&e, cudaEventDisableTiming); return e;
    }();
    static cudaEvent_t ev_join = [] {
        cudaEvent_t e; cudaEventCreateWithFlags(&e, cudaEventDisableTiming); return e;
    }();

    // fork side stream off the main (capture) stream
    cudaEventRecord(ev_fork, 0);
    cudaStreamWaitEvent(s_side, ev_fork, 0);

    // ---- side branch: WkvT first (joined before GEMM), then the q branch ----
    wconvT<<<dim3(1024 / 32, KVD_ / 32), dim3(32, 8), 0, s_side>>>(
        Wkv, wkvT, KVD_, 1024);
    cudaEventRecord(ev_wkv, s_side);
    ln_conv<DIM_><<<BNQ / 8, 256, 0, s_side>>>(x, g_q, b_q, xn);
    wconvT<<<dim3(INNER_ / 32, DIM_ / 32), dim3(32, 8), 0, s_side>>>(
        Wq, wqT, DIM_, INNER_);
    wconvT<<<dim3(DIM_ / 32, INNER_ / 32), dim3(32, 8), 0, s_side>>>(
        Wo, woT, INNER_, DIM_);
    gemm_f16<true><<<dim3(INNER_ / 128, BNQ / 128), 256, GEMM_SMEM, s_side>>>(
        xn, wqT, qbuf, INNER_, DIM_, QSCALE);
    cudaEventRecord(ev_join, s_side);

    // ---- main branch: kv path (ln_kv overlaps WkvT) ----
    ln_conv<KVD_><<<BTM / 8, 256>>>(k_v, g_kv, b_kv, kvn);
    cudaStreamWaitEvent(0, ev_wkv, 0);
    gemm_f16_big<<<dim3(1024 / 128, BTM / 256), 512, BG_SMEM>>>(
        kvn, wkvT, kvp, 1024, KVD_);

    // join: attention needs qbuf (side) + kvp (main); out proj needs woT (side)
    cudaStreamWaitEvent(0, ev_join, 0);

    attention_kernel<<<dim3(BB * HH, NSPLIT), 256, ATT_SMEM>>>(qbuf, kvp, attp, lsum);
    att_reduce<<<BNQ, 256>>>(attp, lsum, att);
    gemm_f16<false><<<dim3(DIM_ / 128, BNQ / 128), 256, GEMM_SMEM>>>(
        att, woT, out, DIM_, INNER_, 1.f);
}